// round 13
// baseline (speedup 1.0000x reference)
#include <cuda_runtime.h>
#include <cuda_fp16.h>
#include <stdint.h>
#include <math.h>

#define CTRLN 256
#define WORDN 128
#define MEMN  128
#define DINN  64
#define BN    512
#define TN    512
#define EPSF  1e-6f

#define STRX 200   // s_inh row stride (halves)
#define STRH 264   // s_hHf row stride (halves)

// fragment-major fp16 weights
__device__ __half gA[16 * 3 * 28 * 256];   // GRU: [mpos][gate][ktile] x 256 halves/tile
__device__ __half gAH[32 * 16 * 256];      // head: [htile][ktile] x 256 halves/tile

// ---------------- helpers ----------------
__device__ __forceinline__ void ffma2(float2 &d, float2 a, float2 b) {
    unsigned long long &du = reinterpret_cast<unsigned long long &>(d);
    unsigned long long au = reinterpret_cast<unsigned long long &>(a);
    unsigned long long bu = reinterpret_cast<unsigned long long &>(b);
    asm("fma.rn.f32x2 %0, %1, %2, %0;" : "+l"(du) : "l"(au), "l"(bu));
}
__device__ __forceinline__ float2 dup2(float a) { return make_float2(a, a); }
__device__ __forceinline__ float sigf(float x) {
    return __fdividef(1.0f, 1.0f + __expf(-x));
}
__device__ __forceinline__ float tanhf_fast(float x) {
    float ax = fabsf(x);
    float t = __expf(-2.0f * ax);
    float r = (1.0f - t) * __fdividef(1.0f, 1.0f + t);
    return copysignf(r, x);
}
__device__ __forceinline__ float softplusf(float x) {
    return fmaxf(x, 0.0f) + log1pf(__expf(-fabsf(x)));
}
__device__ __forceinline__ float sqrt_fast(float x) {
    float xs = x + 1e-30f;
    return xs * rsqrtf(xs);
}
#define BARN(id, cnt) asm volatile("bar.sync %0, %1;" :: "r"(id), "r"(cnt) : "memory")
#define CL_SYNC() do { \
    asm volatile("barrier.cluster.arrive.aligned;" ::: "memory"); \
    asm volatile("barrier.cluster.wait.aligned;" ::: "memory"); \
} while (0)

__device__ __forceinline__ uint32_t ctarank() {
    uint32_t r; asm("mov.u32 %0, %%cluster_ctarank;" : "=r"(r)); return r;
}
__device__ __forceinline__ uint32_t mapa_u32(uint32_t a, uint32_t r) {
    uint32_t d; asm("mapa.shared::cluster.u32 %0, %1, %2;" : "=r"(d) : "r"(a), "r"(r)); return d;
}
__device__ __forceinline__ void stc_h(uint32_t a, __half v) {
    asm volatile("st.shared::cluster.b16 [%0], %1;" :: "r"(a), "h"(__half_as_ushort(v)) : "memory");
}

#define MMA(C, A, B0, B1) \
    asm volatile("mma.sync.aligned.m16n8k16.row.col.f32.f16.f16.f32 " \
        "{%0,%1,%2,%3},{%4,%5,%6,%7},{%8,%9},{%0,%1,%2,%3};" \
        : "+f"((C)[0]), "+f"((C)[1]), "+f"((C)[2]), "+f"((C)[3]) \
        : "r"((A).x), "r"((A).y), "r"((A).z), "r"((A).w), "r"(B0), "r"(B1))

// ---------------- K0: repack weights to fragment-major fp16 ----------------
__global__ void ntm_prep(const float* __restrict__ W_ih, const float* __restrict__ W_hh,
                         const float* __restrict__ W_key, const float* __restrict__ W_beta,
                         const float* __restrict__ W_erase, const float* __restrict__ W_add) {
    int stride = gridDim.x * blockDim.x;
    int idx0 = blockIdx.x * blockDim.x + threadIdx.x;
    for (int i = idx0; i < 16 * 3 * 28 * 256; i += stride) {
        int tile = i >> 8, rem = i & 255;
        int lane = rem >> 3, p = rem & 7;
        int gid = lane >> 2, tig = lane & 3;
        int reg = p >> 1, w = p & 1;
        int r = gid + (reg & 1) * 8;
        int k = 2 * tig + (reg >> 1) * 8 + w;
        int mt = tile / 84, g = (tile / 28) % 3, kt = tile % 28;
        int o = g * 256 + mt * 16 + r;
        float v = (kt < 12) ? W_ih[o * 192 + kt * 16 + k]
                            : W_hh[o * 256 + (kt - 12) * 16 + k];
        gA[i] = __float2half(v);
    }
    for (int i = idx0; i < 32 * 16 * 256; i += stride) {
        int tile = i >> 8, rem = i & 255;
        int lane = rem >> 3, p = rem & 7;
        int gid = lane >> 2, tig = lane & 3;
        int reg = p >> 1, w = p & 1;
        int r = gid + (reg & 1) * 8;
        int k = 2 * tig + (reg >> 1) * 8 + w;
        int ht = tile / 16, kt = tile % 16;
        int o = ht * 16 + r;
        int kk = kt * 16 + k;
        float v = 0.0f;
        if (o < 128)       v = W_key[o * 256 + kk];
        else if (o < 256)  v = W_erase[(o - 128) * 256 + kk];
        else if (o < 384)  v = W_add[(o - 256) * 256 + kk];
        else if (o == 384) v = W_beta[kk];
        gAH[i] = __float2half(v);
    }
}

// SMEM layout offsets (bytes)
#define OFF_INH   0
#define OFF_HHF   3200
#define OFF_RED   7424
#define OFF_REDS  23808
#define OFF_KEY   36096
#define OFF_E     38144
#define OFF_A     40192
#define OFF_W     42240
#define OFF_RACC  44288
#define OFF_READ  48384
#define OFF_BETA  50432
#define OFF_LEN   50448
#define OFF_DST   50480
#define OFF_M     50560
#define SMEM_TOTAL (50560 + 4 * MEMN * WORDN * 2)   // 181632 bytes

// ---------------- K1: cluster-of-2 tensor-core kernel ----------------
__global__ __launch_bounds__(512, 1) __cluster_dims__(2, 1, 1)
void ntm_main(const float* __restrict__ data, const int* __restrict__ batch_sizes,
              const int* __restrict__ unsort_idxs,
              const float* __restrict__ b_ih, const float* __restrict__ b_hh,
              const float* __restrict__ b_key, const float* __restrict__ b_beta,
              const float* __restrict__ b_erase, const float* __restrict__ b_add,
              const float* __restrict__ M0, float* __restrict__ out) {
    extern __shared__ __align__(16) unsigned char dsm[];
    __half* s_inh           = (__half*)(dsm + OFF_INH);   // [8 elem][STRX]: k 0-63 x, 64-191 read
    __half* s_hHf           = (__half*)(dsm + OFF_HHF);   // [8 elem][STRH] fp16 h (full 256 k)
    float*  red             = (float*)(dsm + OFF_RED);    // pipe partials [4 acc][128 jl][8 e]
    float*  redS            = (float*)(dsm + OFF_REDS);   // serial khalf0 partials [3][128][8]
    float (*s_key)[128]     = (float(*)[128])(dsm + OFF_KEY);   // [4 local el][128]
    float (*s_e)[128]       = (float(*)[128])(dsm + OFF_E);
    float (*s_a)[128]       = (float(*)[128])(dsm + OFF_A);
    float (*s_w)[128]       = (float(*)[128])(dsm + OFF_W);
    float (*s_racc)[2][128] = (float(*)[2][128])(dsm + OFF_RACC);
    float (*s_read)[128]    = (float(*)[128])(dsm + OFF_READ);
    float* s_beta           = (float*)(dsm + OFF_BETA);
    int*   s_len            = (int*)(dsm + OFF_LEN);      // [8]
    int*   s_dst            = (int*)(dsm + OFF_DST);      // [8]
    __half* s_M             = (__half*)(dsm + OFF_M);     // [4 local el][128][128]

    const int tid = threadIdx.x;
    const int lane = tid & 31;
    const int warp = tid >> 5;
    const int gid = lane >> 2, tig = lane & 3;
    const uint32_t rank = ctarank();
    const uint32_t peer = rank ^ 1u;
    const int b0blk = (blockIdx.x >> 1) * 8;

    // peer SMEM bases for h / read exchange
    const uint32_t l_inh = (uint32_t)__cvta_generic_to_shared(s_inh);
    const uint32_t l_hHf = (uint32_t)__cvta_generic_to_shared(s_hHf);
    const uint32_t p_inh = mapa_u32(l_inh, peer);
    const uint32_t p_hHf = mapa_u32(l_hHf, peer);

    // ---- active lengths for 8 elems ----
    if (warp < 8) {
        int e = warp, cnt = 0;
        for (int t = lane; t < TN; t += 32) cnt += (batch_sizes[t] > (b0blk + e)) ? 1 : 0;
        #pragma unroll
        for (int s = 16; s; s >>= 1) cnt += __shfl_xor_sync(0xffffffffu, cnt, s);
        if (lane == 0) s_len[e] = cnt;
    }
    // ---- init M in SMEM (local 4 elems) ----
    for (int i = tid; i < (MEMN * WORDN) / 2; i += 512) {
        float2 f = ((const float2*)M0)[i];
        __half2 h = __floats2half2_rn(f.x, f.y);
        #pragma unroll
        for (int el = 0; el < 4; el++)
            ((__half2*)s_M)[el * ((MEMN * WORDN) / 2) + i] = h;
    }
    for (int i = tid; i < 8 * STRX; i += 512) s_inh[i] = __float2half(0.0f);
    for (int i = tid; i < 8 * STRH; i += 512) s_hHf[i] = __float2half(0.0f);

    // ---- per-lane constants ----
    const int mpS = warp >> 1;                     // serial m-tile (local 0-7)
    const int khalf = warp & 1;
    const int mpgS = (int)rank * 8 + mpS;          // global m-tile
    const int jlS = mpS * 16 + gid;                // local j (0-127)
    const int jgS = (int)rank * 128 + jlS;         // global j
    // gates biases (odd warps own gates at jgS, jgS+8)
    const float bR0 = b_ih[jgS] + b_hh[jgS],             bR1 = b_ih[jgS + 8] + b_hh[jgS + 8];
    const float bZ0 = b_ih[256 + jgS] + b_hh[256 + jgS], bZ1 = b_ih[256 + jgS + 8] + b_hh[256 + jgS + 8];
    const float bNi0 = b_ih[512 + jgS],                  bNi1 = b_ih[512 + jgS + 8];
    const float bNh0 = b_hh[512 + jgS],                  bNh1 = b_hh[512 + jgS + 8];
    float bHv[8];
    if (warp < 8) {
        #pragma unroll
        for (int tt = 0; tt < 4; tt++) {
            int o = (warp * 4 + tt) * 16 + gid;
            #pragma unroll
            for (int rr = 0; rr < 2; rr++) {
                int oo = o + rr * 8;
                float v = (oo < 128) ? b_key[oo]
                        : (oo < 256) ? b_erase[oo - 128]
                        : (oo < 384) ? b_add[oo - 256]
                        : ((oo == 384) ? b_beta[0] : 0.0f);
                bHv[2 * tt + rr] = v;
            }
        }
    }
    float hreg[4] = {0.f, 0.f, 0.f, 0.f};          // odd warps: rows jgS/jgS+8, cols 2tig/2tig+1

    // module roles: warps 0-7, 2 warps per local elem
    const int mel = warp >> 1;                      // local elem 0-3 (warps 0-7)
    const int half = warp & 1;
    const int mge = (int)rank * 4 + mel;            // global elem

    // ---- x prefetch (all 8 elems) ----
    const int xe = tid >> 6, xd = tid & 63;
    float xreg = data[((size_t)0 * BN + (b0blk + xe)) * DINN + xd];
    __syncthreads();

    const int Le0 = s_len[2 * tig], Le1 = s_len[2 * tig + 1];
    int Tmax = 0;
    #pragma unroll
    for (int e = 0; e < 8; e++) Tmax = max(Tmax, s_len[e]);

    s_inh[xe * STRX + xd] = __float2half(xreg);
    xreg = data[((size_t)1 * BN + (b0blk + xe)) * DINN + xd];
    __syncthreads();

    // ---- prologue pipe: P_0 = gh(0) + gi_x(x_0) ----
    if (warp >= 8) {
        const int mpP = warp - 8;
        const int mpgP = (int)rank * 8 + mpP;
        const int jlP = mpP * 16 + gid;
        float C[4][4];
        #pragma unroll
        for (int a = 0; a < 4; a++)
            #pragma unroll
            for (int c = 0; c < 4; c++) C[a][c] = 0.0f;
        const uint4* A = (const uint4*)gA;
        #pragma unroll 2
        for (int kt = 0; kt < 4; ++kt) {
            uint32_t b0 = *(const uint32_t*)(s_inh + gid * STRX + kt * 16 + 2 * tig);
            uint32_t b1 = *(const uint32_t*)(s_inh + gid * STRX + kt * 16 + 2 * tig + 8);
            uint4 ar = __ldg(&A[(size_t)((mpgP * 3 + 0) * 28 + kt) * 32 + lane]);
            uint4 az = __ldg(&A[(size_t)((mpgP * 3 + 1) * 28 + kt) * 32 + lane]);
            uint4 an = __ldg(&A[(size_t)((mpgP * 3 + 2) * 28 + kt) * 32 + lane]);
            MMA(C[0], ar, b0, b1); MMA(C[1], az, b0, b1); MMA(C[2], an, b0, b1);
        }
        // gh with h=0 contributes nothing; skip
        #pragma unroll
        for (int a = 0; a < 4; a++) {
            *(float2*)&red[(a * 128 + jlP) * 8 + 2 * tig] = make_float2(C[a][0], C[a][1]);
            *(float2*)&red[(a * 128 + jlP + 8) * 8 + 2 * tig] = make_float2(C[a][2], C[a][3]);
        }
    }
    __syncthreads();
    CL_SYNC();   // both CTAs initialized before any remote writes

    for (int t = 0; t < Tmax; ++t) {
        // ======== SERIAL: gi_read mma, split-k (4 kt per warp) ========
        float Cr[4] = {0, 0, 0, 0}, Cz[4] = {0, 0, 0, 0}, Cni[4] = {0, 0, 0, 0};
        {
            const uint4* A = (const uint4*)gA;
            const int ktb = 4 + 4 * khalf;
            #pragma unroll
            for (int kt = ktb; kt < ktb + 4; ++kt) {
                uint32_t b0 = *(const uint32_t*)(s_inh + gid * STRX + kt * 16 + 2 * tig);
                uint32_t b1 = *(const uint32_t*)(s_inh + gid * STRX + kt * 16 + 2 * tig + 8);
                uint4 ar = __ldg(&A[(size_t)((mpgS * 3 + 0) * 28 + kt) * 32 + lane]);
                uint4 az = __ldg(&A[(size_t)((mpgS * 3 + 1) * 28 + kt) * 32 + lane]);
                uint4 an = __ldg(&A[(size_t)((mpgS * 3 + 2) * 28 + kt) * 32 + lane]);
                MMA(Cr, ar, b0, b1);
                MMA(Cz, az, b0, b1);
                MMA(Cni, an, b0, b1);
            }
        }
        if (khalf == 0) {
            #pragma unroll
            for (int rr = 0; rr < 2; rr++) {
                int jl = jlS + rr * 8;
                *(float2*)&redS[(0 * 128 + jl) * 8 + 2 * tig] = make_float2(Cr[2 * rr], Cr[2 * rr + 1]);
                *(float2*)&redS[(1 * 128 + jl) * 8 + 2 * tig] = make_float2(Cz[2 * rr], Cz[2 * rr + 1]);
                *(float2*)&redS[(2 * 128 + jl) * 8 + 2 * tig] = make_float2(Cni[2 * rr], Cni[2 * rr + 1]);
            }
        }
        __syncthreads();   // B1

        // ---- gates (odd warps) + x-store (all) ----
        if (khalf == 1) {
            #pragma unroll
            for (int c = 0; c < 4; ++c) {
                int rr = (c >> 1) & 1;
                int jl = jlS + rr * 8;
                int jg = jgS + rr * 8;
                int ee = 2 * tig + (c & 1);
                int Lc = (c & 1) ? Le1 : Le0;
                float rp = Cr[c]  + redS[(0 * 128 + jl) * 8 + ee] + red[(0 * 128 + jl) * 8 + ee] + (rr ? bR1 : bR0);
                float zp = Cz[c]  + redS[(1 * 128 + jl) * 8 + ee] + red[(1 * 128 + jl) * 8 + ee] + (rr ? bZ1 : bZ0);
                float np = Cni[c] + redS[(2 * 128 + jl) * 8 + ee] + red[(2 * 128 + jl) * 8 + ee] + (rr ? bNi1 : bNi0);
                float nh = red[(3 * 128 + jl) * 8 + ee] + (rr ? bNh1 : bNh0);
                float r = sigf(rp);
                float z = sigf(zp);
                float n = tanhf_fast(np + r * nh);
                float h = (1.0f - z) * n + z * hreg[c];
                if (t < Lc) hreg[c] = h;
                __half hh = __float2half(hreg[c]);
                s_hHf[ee * STRH + jg] = hh;
                stc_h(p_hHf + (uint32_t)(ee * STRH + jg) * 2u, hh);
            }
        }
        // x_{t+1} -> smem (local), prefetch x_{t+2}
        s_inh[xe * STRX + xd] = __float2half(xreg);
        {
            int tn = min(t + 2, TN - 1);
            xreg = data[((size_t)tn * BN + (b0blk + xe)) * DINN + xd];
        }
        CL_SYNC();   // fork: full h visible in both CTAs

        // ======== PARALLEL ========
        if (warp >= 8) {
            // pipe: P_{t+1} = gh(h_t) + gi_x(x_{t+1}), 1 m-tile per warp
            const int mpP = warp - 8;
            const int mpgP = (int)rank * 8 + mpP;
            const int jlP = mpP * 16 + gid;
            float C[4][4];
            #pragma unroll
            for (int a = 0; a < 4; a++)
                #pragma unroll
                for (int c = 0; c < 4; c++) C[a][c] = 0.0f;
            const uint4* A = (const uint4*)gA;
            #pragma unroll 2
            for (int kt = 0; kt < 4; ++kt) {
                uint32_t b0 = *(const uint32_t*)(s_inh + gid * STRX + kt * 16 + 2 * tig);
                uint32_t b1 = *(const uint32_t*)(s_inh + gid * STRX + kt * 16 + 2 * tig + 8);
                uint4 ar = __ldg(&A[(size_t)((mpgP * 3 + 0) * 28 + kt) * 32 + lane]);
                uint4 az = __ldg(&A[(size_t)((mpgP * 3 + 1) * 28 + kt) * 32 + lane]);
                uint4 an = __ldg(&A[(size_t)((mpgP * 3 + 2) * 28 + kt) * 32 + lane]);
                MMA(C[0], ar, b0, b1); MMA(C[1], az, b0, b1); MMA(C[2], an, b0, b1);
            }
            #pragma unroll 2
            for (int kt = 0; kt < 16; ++kt) {
                uint32_t b0 = *(const uint32_t*)(s_hHf + gid * STRH + kt * 16 + 2 * tig);
                uint32_t b1 = *(const uint32_t*)(s_hHf + gid * STRH + kt * 16 + 2 * tig + 8);
                uint4 ar = __ldg(&A[(size_t)((mpgP * 3 + 0) * 28 + 12 + kt) * 32 + lane]);
                uint4 az = __ldg(&A[(size_t)((mpgP * 3 + 1) * 28 + 12 + kt) * 32 + lane]);
                uint4 an = __ldg(&A[(size_t)((mpgP * 3 + 2) * 28 + 12 + kt) * 32 + lane]);
                MMA(C[0], ar, b0, b1); MMA(C[1], az, b0, b1); MMA(C[3], an, b0, b1);
            }
            #pragma unroll
            for (int a = 0; a < 4; a++) {
                *(float2*)&red[(a * 128 + jlP) * 8 + 2 * tig] = make_float2(C[a][0], C[a][1]);
                *(float2*)&red[(a * 128 + jlP + 8) * 8 + 2 * tig] = make_float2(C[a][2], C[a][3]);
            }
        } else {
            // ---- head mma: full 512 outputs, extract local 4 elems ----
            float CH[4][4];
            #pragma unroll
            for (int tt = 0; tt < 4; tt++)
                #pragma unroll
                for (int c = 0; c < 4; c++) CH[tt][c] = 0.0f;
            const uint4* AH = (const uint4*)gAH;
            #pragma unroll 2
            for (int kt = 0; kt < 16; ++kt) {
                uint32_t b0 = *(const uint32_t*)(s_hHf + gid * STRH + kt * 16 + 2 * tig);
                uint32_t b1 = *(const uint32_t*)(s_hHf + gid * STRH + kt * 16 + 2 * tig + 8);
                #pragma unroll
                for (int tt = 0; tt < 4; tt++) {
                    uint4 a = __ldg(&AH[(size_t)((warp * 4 + tt) * 16 + kt) * 32 + lane]);
                    MMA(CH[tt], a, b0, b1);
                }
            }
            if ((tig >> 1) == (int)rank) {
                #pragma unroll
                for (int tt = 0; tt < 4; tt++) {
                    int obase = (warp * 4 + tt) * 16 + gid;
                    #pragma unroll
                    for (int c = 0; c < 4; c++) {
                        int o = obase + ((c & 2) ? 8 : 0);
                        int el = 2 * tig + (c & 1) - (int)rank * 4;
                        float v = CH[tt][c] + bHv[2 * tt + ((c >> 1) & 1)];
                        if (o < 128)       s_key[el][o] = tanhf_fast(v);
                        else if (o < 256)  s_e[el][o - 128] = sigf(v);
                        else if (o < 384)  s_a[el][o - 256] = v;
                        else if (o == 384) s_beta[el] = softplusf(v);
                    }
                }
            }
            BARN(5, 256);

            // ---- memory module: 2 warps per local elem ----
            if (t < s_len[mge]) {
                const __half* Me = s_M + mel * (MEMN * WORDN);
                {
                    int rl = lane >> 3;
                    int cc = (lane & 7) * 16;
                    float2 kx[8];
                    #pragma unroll
                    for (int i = 0; i < 8; i++)
                        kx[i] = make_float2(s_key[mel][cc + 2 * i], s_key[mel][cc + 2 * i + 1]);
                    #pragma unroll 4
                    for (int mb = half * 64; mb < half * 64 + 64; mb += 4) {
                        int m = mb + rl;
                        const uint4* Mr = (const uint4*)(Me + m * WORDN + cc);
                        uint4 u0 = Mr[0];
                        uint4 u1 = Mr[1];
                        const __half2* p0 = (const __half2*)&u0;
                        const __half2* p1 = (const __half2*)&u1;
                        float2 d2 = make_float2(0.f, 0.f), n2 = make_float2(0.f, 0.f);
                        #pragma unroll
                        for (int q = 0; q < 4; q++) {
                            float2 f0 = __half22float2(p0[q]);
                            float2 f1 = __half22float2(p1[q]);
                            ffma2(d2, f0, kx[q]);
                            ffma2(n2, f0, f0);
                            ffma2(d2, f1, kx[4 + q]);
                            ffma2(n2, f1, f1);
                        }
                        float dot = d2.x + d2.y, nrm = n2.x + n2.y;
                        #pragma unroll
                        for (int s = 1; s < 8; s <<= 1) {
                            dot += __shfl_xor_sync(0xffffffffu, dot, s);
                            nrm += __shfl_xor_sync(0xffffffffu, nrm, s);
                        }
                        if ((lane & 7) == 0) s_w[mel][m] = __fdividef(dot, sqrt_fast(nrm) + EPSF);
                    }
                }
                BARN(1 + mel, 64);
                if (half == 0) {
                    float q0 = s_key[mel][lane];
                    float q1 = s_key[mel][lane + 32];
                    float q2 = s_key[mel][lane + 64];
                    float q3 = s_key[mel][lane + 96];
                    float ss = q0 * q0 + q1 * q1 + q2 * q2 + q3 * q3;
                    #pragma unroll
                    for (int s = 16; s; s >>= 1) ss += __shfl_xor_sync(0xffffffffu, ss, s);
                    float scale = __fdividef(s_beta[mel], sqrt_fast(ss) + EPSF);
                    float v0 = scale * s_w[mel][lane];
                    float v1 = scale * s_w[mel][lane + 32];
                    float v2 = scale * s_w[mel][lane + 64];
                    float v3 = scale * s_w[mel][lane + 96];
                    float mx = fmaxf(fmaxf(v0, v1), fmaxf(v2, v3));
                    #pragma unroll
                    for (int s = 16; s; s >>= 1) mx = fmaxf(mx, __shfl_xor_sync(0xffffffffu, mx, s));
                    v0 = __expf(v0 - mx); v1 = __expf(v1 - mx);
                    v2 = __expf(v2 - mx); v3 = __expf(v3 - mx);
                    float sum = v0 + v1 + v2 + v3;
                    #pragma unroll
                    for (int s = 16; s; s >>= 1) sum += __shfl_xor_sync(0xffffffffu, sum, s);
                    float inv = __fdividef(1.0f, sum);
                    s_w[mel][lane] = v0 * inv;
                    s_w[mel][lane + 32] = v1 * inv;
                    s_w[mel][lane + 64] = v2 * inv;
                    s_w[mel][lane + 96] = v3 * inv;
                }
                BARN(1 + mel, 64);
                {
                    __half* Mw = s_M + mel * (MEMN * WORDN) + lane * 4;
                    float4 e4 = *(const float4*)&s_e[mel][lane * 4];
                    float4 a4 = *(const float4*)&s_a[mel][lane * 4];
                    float2 en01 = make_float2(-e4.x, -e4.y), en23 = make_float2(-e4.z, -e4.w);
                    float2 a01 = make_float2(a4.x, a4.y),    a23 = make_float2(a4.z, a4.w);
                    float2 r01 = make_float2(0.f, 0.f), r23 = make_float2(0.f, 0.f);
                    #pragma unroll 8
                    for (int m = half * 64; m < half * 64 + 64; ++m) {
                        float wm = s_w[mel][m];
                        float2 wm2 = dup2(wm);
                        uint2 u = *(uint2*)(Mw + m * WORDN);
                        __half2* hp = (__half2*)&u;
                        float2 m01 = __half22float2(hp[0]);
                        float2 m23 = __half22float2(hp[1]);
                        ffma2(r01, wm2, m01);
                        ffma2(r23, wm2, m23);
                        float2 f01 = make_float2(1.f, 1.f), f23 = make_float2(1.f, 1.f);
                        ffma2(f01, wm2, en01);
                        ffma2(f23, wm2, en23);
                        float2 w01 = make_float2(0.f, 0.f), w23 = make_float2(0.f, 0.f);
                        ffma2(w01, wm2, a01);
                        ffma2(w23, wm2, a23);
                        ffma2(w01, m01, f01);
                        ffma2(w23, m23, f23);
                        hp[0] = __floats2half2_rn(w01.x, w01.y);
                        hp[1] = __floats2half2_rn(w23.x, w23.y);
                        *(uint2*)(Mw + m * WORDN) = u;
                    }
                    *(float4*)&s_racc[mel][half][lane * 4] = make_float4(r01.x, r01.y, r23.x, r23.y);
                }
                BARN(1 + mel, 64);
                // combine read halves -> s_read + s_inh (local + remote)
                {
                    int w = half * 32 + lane;
                    float s1 = s_racc[mel][0][w] + s_racc[mel][1][w];
                    s_read[mel][w] = s1;
                    __half h1 = __float2half(s1);
                    s_inh[mge * STRX + 64 + w] = h1;
                    stc_h(p_inh + (uint32_t)(mge * STRX + 64 + w) * 2u, h1);
                    int w2 = w + 64;
                    float s2 = s_racc[mel][0][w2] + s_racc[mel][1][w2];
                    s_read[mel][w2] = s2;
                    __half h2 = __float2half(s2);
                    s_inh[mge * STRX + 64 + w2] = h2;
                    stc_h(p_inh + (uint32_t)(mge * STRX + 64 + w2) * 2u, h2);
                }
            }
        }
        CL_SYNC();   // end of step: read rows visible in both CTAs
    }

    // ---- epilogue ----
    for (int q = tid; q < BN; q += 512) {
        int u = unsort_idxs[q];
        if (u >= b0blk && u < b0blk + 8) s_dst[u - b0blk] = q;
    }
    __syncthreads();
    if (khalf == 1) {
        #pragma unroll
        for (int c = 0; c < 4; ++c) {
            int jg = jgS + ((c & 2) ? 8 : 0);
            int ee = 2 * tig + (c & 1);
            out[(size_t)s_dst[ee] * CTRLN + jg] = hreg[c];
        }
    }
    {
        int el = tid >> 7, w = tid & 127;
        int ge = (int)rank * 4 + el;
        out[(size_t)BN * CTRLN + (size_t)s_dst[ge] * WORDN + w] = s_read[el][w];
    }
}

// ---------------- launch ----------------
extern "C" void kernel_launch(void* const* d_in, const int* in_sizes, int n_in,
                              void* d_out, int out_size) {
    const float* data        = (const float*)d_in[0];
    const int*   batch_sizes = (const int*)d_in[1];
    const int*   unsort      = (const int*)d_in[2];
    const float* W_ih        = (const float*)d_in[3];
    const float* b_ih        = (const float*)d_in[4];
    const float* W_hh        = (const float*)d_in[5];
    const float* b_hh        = (const float*)d_in[6];
    const float* W_key       = (const float*)d_in[7];
    const float* b_key       = (const float*)d_in[8];
    const float* W_beta      = (const float*)d_in[9];
    const float* b_beta      = (const float*)d_in[10];
    const float* W_erase     = (const float*)d_in[11];
    const float* b_erase     = (const float*)d_in[12];
    const float* W_add       = (const float*)d_in[13];
    const float* b_add       = (const float*)d_in[14];
    const float* M0          = (const float*)d_in[15];

    cudaFuncSetAttribute(ntm_main, cudaFuncAttributeMaxDynamicSharedMemorySize, SMEM_TOTAL);
    ntm_prep<<<256, 256>>>(W_ih, W_hh, W_key, W_beta, W_erase, W_add);
    ntm_main<<<128, 512, SMEM_TOTAL>>>(data, batch_sizes, unsort,
                                       b_ih, b_hh, b_key, b_beta, b_erase, b_add,
                                       M0, (float*)d_out);
}

// round 14
// speedup vs baseline: 1.0303x; 1.0303x over previous
#include <cuda_runtime.h>
#include <cuda_fp16.h>
#include <stdint.h>
#include <math.h>

#define CTRLN 256
#define WORDN 128
#define MEMN  128
#define DINN  64
#define BN    512
#define TN    512
#define EPSF  1e-6f

#define STRX 200   // s_inh row stride (halves)
#define STRH 264   // s_hHf row stride (halves)

// fragment-major fp16 weights
__device__ __half gA[16 * 3 * 28 * 256];   // GRU: [mpos][gate][ktile] x 256 halves/tile
__device__ __half gAH[32 * 16 * 256];      // head: [htile][ktile] x 256 halves/tile

// ---------------- helpers ----------------
__device__ __forceinline__ void ffma2(float2 &d, float2 a, float2 b) {
    unsigned long long &du = reinterpret_cast<unsigned long long &>(d);
    unsigned long long au = reinterpret_cast<unsigned long long &>(a);
    unsigned long long bu = reinterpret_cast<unsigned long long &>(b);
    asm("fma.rn.f32x2 %0, %1, %2, %0;" : "+l"(du) : "l"(au), "l"(bu));
}
__device__ __forceinline__ float2 dup2(float a) { return make_float2(a, a); }
__device__ __forceinline__ float sigf(float x) {
    return __fdividef(1.0f, 1.0f + __expf(-x));
}
__device__ __forceinline__ float tanhf_fast(float x) {
    float ax = fabsf(x);
    float t = __expf(-2.0f * ax);
    float r = (1.0f - t) * __fdividef(1.0f, 1.0f + t);
    return copysignf(r, x);
}
__device__ __forceinline__ float softplusf(float x) {
    return fmaxf(x, 0.0f) + log1pf(__expf(-fabsf(x)));
}
__device__ __forceinline__ float sqrt_fast(float x) {
    float xs = x + 1e-30f;
    return xs * rsqrtf(xs);
}
#define BARN(id, cnt) asm volatile("bar.sync %0, %1;" :: "r"(id), "r"(cnt) : "memory")
#define CL_SYNC() do { \
    asm volatile("barrier.cluster.arrive.aligned;" ::: "memory"); \
    asm volatile("barrier.cluster.wait.aligned;" ::: "memory"); \
} while (0)

__device__ __forceinline__ uint32_t ctarank() {
    uint32_t r; asm("mov.u32 %0, %%cluster_ctarank;" : "=r"(r)); return r;
}
__device__ __forceinline__ uint32_t mapa_u32(uint32_t a, uint32_t r) {
    uint32_t d; asm("mapa.shared::cluster.u32 %0, %1, %2;" : "=r"(d) : "r"(a), "r"(r)); return d;
}
__device__ __forceinline__ void stc_h(uint32_t a, __half v) {
    asm volatile("st.shared::cluster.b16 [%0], %1;" :: "r"(a), "h"(__half_as_ushort(v)) : "memory");
}
__device__ __forceinline__ void stc_f(uint32_t a, float v) {
    asm volatile("st.shared::cluster.f32 [%0], %1;" :: "r"(a), "f"(v) : "memory");
}

#define MMA(C, A, B0, B1) \
    asm volatile("mma.sync.aligned.m16n8k16.row.col.f32.f16.f16.f32 " \
        "{%0,%1,%2,%3},{%4,%5,%6,%7},{%8,%9},{%0,%1,%2,%3};" \
        : "+f"((C)[0]), "+f"((C)[1]), "+f"((C)[2]), "+f"((C)[3]) \
        : "r"((A).x), "r"((A).y), "r"((A).z), "r"((A).w), "r"(B0), "r"(B1))

// ---------------- K0: repack weights to fragment-major fp16 ----------------
__global__ void ntm_prep(const float* __restrict__ W_ih, const float* __restrict__ W_hh,
                         const float* __restrict__ W_key, const float* __restrict__ W_beta,
                         const float* __restrict__ W_erase, const float* __restrict__ W_add) {
    int stride = gridDim.x * blockDim.x;
    int idx0 = blockIdx.x * blockDim.x + threadIdx.x;
    for (int i = idx0; i < 16 * 3 * 28 * 256; i += stride) {
        int tile = i >> 8, rem = i & 255;
        int lane = rem >> 3, p = rem & 7;
        int gid = lane >> 2, tig = lane & 3;
        int reg = p >> 1, w = p & 1;
        int r = gid + (reg & 1) * 8;
        int k = 2 * tig + (reg >> 1) * 8 + w;
        int mt = tile / 84, g = (tile / 28) % 3, kt = tile % 28;
        int o = g * 256 + mt * 16 + r;
        float v = (kt < 12) ? W_ih[o * 192 + kt * 16 + k]
                            : W_hh[o * 256 + (kt - 12) * 16 + k];
        gA[i] = __float2half(v);
    }
    for (int i = idx0; i < 32 * 16 * 256; i += stride) {
        int tile = i >> 8, rem = i & 255;
        int lane = rem >> 3, p = rem & 7;
        int gid = lane >> 2, tig = lane & 3;
        int reg = p >> 1, w = p & 1;
        int r = gid + (reg & 1) * 8;
        int k = 2 * tig + (reg >> 1) * 8 + w;
        int ht = tile / 16, kt = tile % 16;
        int o = ht * 16 + r;
        int kk = kt * 16 + k;
        float v = 0.0f;
        if (o < 128)       v = W_key[o * 256 + kk];
        else if (o < 256)  v = W_erase[(o - 128) * 256 + kk];
        else if (o < 384)  v = W_add[(o - 256) * 256 + kk];
        else if (o == 384) v = W_beta[kk];
        gAH[i] = __float2half(v);
    }
}

// SMEM layout offsets (bytes)
#define OFF_INH   0
#define OFF_HHF   3200
#define OFF_RED   7424
#define OFF_REDS  23808
#define OFF_KEY   36096
#define OFF_E     38144
#define OFF_A     40192
#define OFF_W     42240
#define OFF_RACC  44288
#define OFF_READ  48384
#define OFF_BETA  50432
#define OFF_LEN   50448
#define OFF_DST   50480
#define OFF_MBAR  50512
#define OFF_M     50560
#define SMEM_TOTAL (50560 + 4 * MEMN * WORDN * 2)   // 181632 bytes

// ---------------- K1: cluster-of-2 tensor-core kernel, head split ----------------
__global__ __launch_bounds__(512, 1) __cluster_dims__(2, 1, 1)
void ntm_main(const float* __restrict__ data, const int* __restrict__ batch_sizes,
              const int* __restrict__ unsort_idxs,
              const float* __restrict__ b_ih, const float* __restrict__ b_hh,
              const float* __restrict__ b_key, const float* __restrict__ b_beta,
              const float* __restrict__ b_erase, const float* __restrict__ b_add,
              const float* __restrict__ M0, float* __restrict__ out) {
    extern __shared__ __align__(16) unsigned char dsm[];
    __half* s_inh           = (__half*)(dsm + OFF_INH);   // [8 elem][STRX]
    __half* s_hHf           = (__half*)(dsm + OFF_HHF);   // [8 elem][STRH]
    float*  red             = (float*)(dsm + OFF_RED);    // pipe partials [4][128 jl][8 e]
    float*  redS            = (float*)(dsm + OFF_REDS);   // serial khalf0 partials [3][128][8]
    float (*s_key)[128]     = (float(*)[128])(dsm + OFF_KEY);   // [4 local el][128]
    float (*s_e)[128]       = (float(*)[128])(dsm + OFF_E);
    float (*s_a)[128]       = (float(*)[128])(dsm + OFF_A);
    float (*s_w)[128]       = (float(*)[128])(dsm + OFF_W);
    float (*s_racc)[2][128] = (float(*)[2][128])(dsm + OFF_RACC);
    float (*s_read)[128]    = (float(*)[128])(dsm + OFF_READ);
    float* s_beta           = (float*)(dsm + OFF_BETA);
    int*   s_len            = (int*)(dsm + OFF_LEN);
    int*   s_dst            = (int*)(dsm + OFF_DST);
    __half* s_M             = (__half*)(dsm + OFF_M);     // [4 local el][128][128]

    const int tid = threadIdx.x;
    const int lane = tid & 31;
    const int warp = tid >> 5;
    const int gid = lane >> 2, tig = lane & 3;
    const uint32_t rank = ctarank();
    const uint32_t peer = rank ^ 1u;
    const int b0blk = (blockIdx.x >> 1) * 8;

    const uint32_t l_base = (uint32_t)__cvta_generic_to_shared(dsm);
    const uint32_t p_base = mapa_u32(l_base, peer);
    const uint32_t l_mbar = l_base + OFF_MBAR;
    const uint32_t p_mbar = p_base + OFF_MBAR;
    const uint32_t p_inh  = p_base + OFF_INH;
    const uint32_t p_hHf  = p_base + OFF_HHF;

    // ---- active lengths for 8 elems ----
    if (warp < 8) {
        int e = warp, cnt = 0;
        for (int t = lane; t < TN; t += 32) cnt += (batch_sizes[t] > (b0blk + e)) ? 1 : 0;
        #pragma unroll
        for (int s = 16; s; s >>= 1) cnt += __shfl_xor_sync(0xffffffffu, cnt, s);
        if (lane == 0) s_len[e] = cnt;
    }
    // ---- init M in SMEM (local 4 elems) ----
    for (int i = tid; i < (MEMN * WORDN) / 2; i += 512) {
        float2 f = ((const float2*)M0)[i];
        __half2 h = __floats2half2_rn(f.x, f.y);
        #pragma unroll
        for (int el = 0; el < 4; el++)
            ((__half2*)s_M)[el * ((MEMN * WORDN) / 2) + i] = h;
    }
    for (int i = tid; i < 8 * STRX; i += 512) s_inh[i] = __float2half(0.0f);
    for (int i = tid; i < 8 * STRH; i += 512) s_hHf[i] = __float2half(0.0f);
    if (tid == 0) {
        asm volatile("mbarrier.init.shared.b64 [%0], %1;" :: "r"(l_mbar), "r"(8) : "memory");
    }

    // ---- per-lane constants ----
    const int mpS = warp >> 1;                     // serial m-tile (local 0-7)
    const int khalf = warp & 1;
    const int mpgS = (int)rank * 8 + mpS;
    const int jlS = mpS * 16 + gid;
    const int jgS = (int)rank * 128 + jlS;
    const float bR0 = b_ih[jgS] + b_hh[jgS],             bR1 = b_ih[jgS + 8] + b_hh[jgS + 8];
    const float bZ0 = b_ih[256 + jgS] + b_hh[256 + jgS], bZ1 = b_ih[256 + jgS + 8] + b_hh[256 + jgS + 8];
    const float bNi0 = b_ih[512 + jgS],                  bNi1 = b_ih[512 + jgS + 8];
    const float bNh0 = b_hh[512 + jgS],                  bNh1 = b_hh[512 + jgS + 8];
    // head biases: 2 h-tiles per warp (ht = rank*16 + warp*2 + tt), o = ht*16+gid+rr*8
    float bHv[4];
    if (warp < 8) {
        #pragma unroll
        for (int tt = 0; tt < 2; tt++) {
            int ht = (int)rank * 16 + warp * 2 + tt;
            #pragma unroll
            for (int rr = 0; rr < 2; rr++) {
                int oo = ht * 16 + gid + rr * 8;
                float v = (oo < 128) ? b_key[oo]
                        : (oo < 256) ? b_erase[oo - 128]
                        : (oo < 384) ? b_add[oo - 256]
                        : ((oo == 384) ? b_beta[0] : 0.0f);
                bHv[tt * 2 + rr] = v;
            }
        }
    }
    float hreg[4] = {0.f, 0.f, 0.f, 0.f};

    // module roles: warps 0-7, 2 warps per local elem
    const int mel = warp >> 1;
    const int half = warp & 1;
    const int mge = (int)rank * 4 + mel;
    int mph = 0;   // mbar phase (warps 0-7)

    // ---- x prefetch ----
    const int xe = tid >> 6, xd = tid & 63;
    float xreg = data[((size_t)0 * BN + (b0blk + xe)) * DINN + xd];
    __syncthreads();

    const int Le0 = s_len[2 * tig], Le1 = s_len[2 * tig + 1];
    int Tmax = 0;
    #pragma unroll
    for (int e = 0; e < 8; e++) Tmax = max(Tmax, s_len[e]);

    s_inh[xe * STRX + xd] = __float2half(xreg);
    xreg = data[((size_t)1 * BN + (b0blk + xe)) * DINN + xd];
    __syncthreads();

    // ---- prologue pipe: P_0 = gi_x(x_0) (h=0) ----
    if (warp >= 8) {
        const int mpP = warp - 8;
        const int mpgP = (int)rank * 8 + mpP;
        const int jlP = mpP * 16 + gid;
        float C[4][4];
        #pragma unroll
        for (int a = 0; a < 4; a++)
            #pragma unroll
            for (int c = 0; c < 4; c++) C[a][c] = 0.0f;
        const uint4* A = (const uint4*)gA;
        #pragma unroll 2
        for (int kt = 0; kt < 4; ++kt) {
            uint32_t b0 = *(const uint32_t*)(s_inh + gid * STRX + kt * 16 + 2 * tig);
            uint32_t b1 = *(const uint32_t*)(s_inh + gid * STRX + kt * 16 + 2 * tig + 8);
            uint4 ar = __ldg(&A[(size_t)((mpgP * 3 + 0) * 28 + kt) * 32 + lane]);
            uint4 az = __ldg(&A[(size_t)((mpgP * 3 + 1) * 28 + kt) * 32 + lane]);
            uint4 an = __ldg(&A[(size_t)((mpgP * 3 + 2) * 28 + kt) * 32 + lane]);
            MMA(C[0], ar, b0, b1); MMA(C[1], az, b0, b1); MMA(C[2], an, b0, b1);
        }
        #pragma unroll
        for (int a = 0; a < 4; a++) {
            *(float2*)&red[(a * 128 + jlP) * 8 + 2 * tig] = make_float2(C[a][0], C[a][1]);
            *(float2*)&red[(a * 128 + jlP + 8) * 8 + 2 * tig] = make_float2(C[a][2], C[a][3]);
        }
    }
    __syncthreads();
    CL_SYNC();   // init + prologue visible cluster-wide

    for (int t = 0; t < Tmax; ++t) {
        // ======== SERIAL: gi_read mma, split-k (4 kt per warp) ========
        float Cr[4] = {0, 0, 0, 0}, Cz[4] = {0, 0, 0, 0}, Cni[4] = {0, 0, 0, 0};
        {
            const uint4* A = (const uint4*)gA;
            const int ktb = 4 + 4 * khalf;
            #pragma unroll
            for (int kt = ktb; kt < ktb + 4; ++kt) {
                uint32_t b0 = *(const uint32_t*)(s_inh + gid * STRX + kt * 16 + 2 * tig);
                uint32_t b1 = *(const uint32_t*)(s_inh + gid * STRX + kt * 16 + 2 * tig + 8);
                uint4 ar = __ldg(&A[(size_t)((mpgS * 3 + 0) * 28 + kt) * 32 + lane]);
                uint4 az = __ldg(&A[(size_t)((mpgS * 3 + 1) * 28 + kt) * 32 + lane]);
                uint4 an = __ldg(&A[(size_t)((mpgS * 3 + 2) * 28 + kt) * 32 + lane]);
                MMA(Cr, ar, b0, b1);
                MMA(Cz, az, b0, b1);
                MMA(Cni, an, b0, b1);
            }
        }
        if (khalf == 0) {
            #pragma unroll
            for (int rr = 0; rr < 2; rr++) {
                int jl = jlS + rr * 8;
                *(float2*)&redS[(0 * 128 + jl) * 8 + 2 * tig] = make_float2(Cr[2 * rr], Cr[2 * rr + 1]);
                *(float2*)&redS[(1 * 128 + jl) * 8 + 2 * tig] = make_float2(Cz[2 * rr], Cz[2 * rr + 1]);
                *(float2*)&redS[(2 * 128 + jl) * 8 + 2 * tig] = make_float2(Cni[2 * rr], Cni[2 * rr + 1]);
            }
        }
        __syncthreads();   // B1

        // ---- gates (odd warps) + x-store (all) ----
        if (khalf == 1) {
            #pragma unroll
            for (int c = 0; c < 4; ++c) {
                int rr = (c >> 1) & 1;
                int jl = jlS + rr * 8;
                int jg = jgS + rr * 8;
                int ee = 2 * tig + (c & 1);
                int Lc = (c & 1) ? Le1 : Le0;
                float rp = Cr[c]  + redS[(0 * 128 + jl) * 8 + ee] + red[(0 * 128 + jl) * 8 + ee] + (rr ? bR1 : bR0);
                float zp = Cz[c]  + redS[(1 * 128 + jl) * 8 + ee] + red[(1 * 128 + jl) * 8 + ee] + (rr ? bZ1 : bZ0);
                float np = Cni[c] + redS[(2 * 128 + jl) * 8 + ee] + red[(2 * 128 + jl) * 8 + ee] + (rr ? bNi1 : bNi0);
                float nh = red[(3 * 128 + jl) * 8 + ee] + (rr ? bNh1 : bNh0);
                float r = sigf(rp);
                float z = sigf(zp);
                float n = tanhf_fast(np + r * nh);
                float h = (1.0f - z) * n + z * hreg[c];
                if (t < Lc) hreg[c] = h;
                __half hh = __float2half(hreg[c]);
                s_hHf[ee * STRH + jg] = hh;
                stc_h(p_hHf + (uint32_t)(ee * STRH + jg) * 2u, hh);
            }
        }
        s_inh[xe * STRX + xd] = __float2half(xreg);
        {
            int tn = min(t + 2, TN - 1);
            xreg = data[((size_t)tn * BN + (b0blk + xe)) * DINN + xd];
        }
        CL_SYNC();   // fork: full h visible in both CTAs

        // ======== PARALLEL ========
        if (warp >= 8) {
            // pipe: P_{t+1} = gh(h_t) + gi_x(x_{t+1}), 1 m-tile per warp
            const int mpP = warp - 8;
            const int mpgP = (int)rank * 8 + mpP;
            const int jlP = mpP * 16 + gid;
            float C[4][4];
            #pragma unroll
            for (int a = 0; a < 4; a++)
                #pragma unroll
                for (int c = 0; c < 4; c++) C[a][c] = 0.0f;
            const uint4* A = (const uint4*)gA;
            #pragma unroll 2
            for (int kt = 0; kt < 4; ++kt) {
                uint32_t b0 = *(const uint32_t*)(s_inh + gid * STRX + kt * 16 + 2 * tig);
                uint32_t b1 = *(const uint32_t*)(s_inh + gid * STRX + kt * 16 + 2 * tig + 8);
                uint4 ar = __ldg(&A[(size_t)((mpgP * 3 + 0) * 28 + kt) * 32 + lane]);
                uint4 az = __ldg(&A[(size_t)((mpgP * 3 + 1) * 28 + kt) * 32 + lane]);
                uint4 an = __ldg(&A[(size_t)((mpgP * 3 + 2) * 28 + kt) * 32 + lane]);
                MMA(C[0], ar, b0, b1); MMA(C[1], az, b0, b1); MMA(C[2], an, b0, b1);
            }
            #pragma unroll 2
            for (int kt = 0; kt < 16; ++kt) {
                uint32_t b0 = *(const uint32_t*)(s_hHf + gid * STRH + kt * 16 + 2 * tig);
                uint32_t b1 = *(const uint32_t*)(s_hHf + gid * STRH + kt * 16 + 2 * tig + 8);
                uint4 ar = __ldg(&A[(size_t)((mpgP * 3 + 0) * 28 + 12 + kt) * 32 + lane]);
                uint4 az = __ldg(&A[(size_t)((mpgP * 3 + 1) * 28 + 12 + kt) * 32 + lane]);
                uint4 an = __ldg(&A[(size_t)((mpgP * 3 + 2) * 28 + 12 + kt) * 32 + lane]);
                MMA(C[0], ar, b0, b1); MMA(C[1], az, b0, b1); MMA(C[3], an, b0, b1);
            }
            #pragma unroll
            for (int a = 0; a < 4; a++) {
                *(float2*)&red[(a * 128 + jlP) * 8 + 2 * tig] = make_float2(C[a][0], C[a][1]);
                *(float2*)&red[(a * 128 + jlP + 8) * 8 + 2 * tig] = make_float2(C[a][2], C[a][3]);
            }
        } else {
            // ---- head mma: 2 h-tiles per warp (this CTA's 256 output rows, all 8 elems) ----
            float CH[2][4];
            #pragma unroll
            for (int tt = 0; tt < 2; tt++)
                #pragma unroll
                for (int c = 0; c < 4; c++) CH[tt][c] = 0.0f;
            const uint4* AH = (const uint4*)gAH;
            const int htb = (int)rank * 16 + warp * 2;
            #pragma unroll 2
            for (int kt = 0; kt < 16; ++kt) {
                uint32_t b0 = *(const uint32_t*)(s_hHf + gid * STRH + kt * 16 + 2 * tig);
                uint32_t b1 = *(const uint32_t*)(s_hHf + gid * STRH + kt * 16 + 2 * tig + 8);
                #pragma unroll
                for (int tt = 0; tt < 2; tt++) {
                    uint4 a = __ldg(&AH[(size_t)((htb + tt) * 16 + kt) * 32 + lane]);
                    MMA(CH[tt], a, b0, b1);
                }
            }
            // route outputs: local elems -> local arrays; peer elems -> stc
            #pragma unroll
            for (int tt = 0; tt < 2; tt++) {
                #pragma unroll
                for (int c = 0; c < 4; c++) {
                    int o = (htb + tt) * 16 + gid + ((c >> 1) << 3);
                    int e = 2 * tig + (c & 1);
                    float v = CH[tt][c] + bHv[tt * 2 + (c >> 1)];
                    if (o <= 384) {
                        float w;
                        int off;
                        if (o < 128)      { w = tanhf_fast(v); off = OFF_KEY + ((e & 3) * 128 + o) * 4; }
                        else if (o < 256) { w = sigf(v);       off = OFF_E + ((e & 3) * 128 + o - 128) * 4; }
                        else if (o < 384) { w = v;             off = OFF_A + ((e & 3) * 128 + o - 256) * 4; }
                        else              { w = softplusf(v);  off = OFF_BETA + (e & 3) * 4; }
                        if ((e >> 2) == (int)rank) *(float*)(dsm + off) = w;
                        else stc_f(p_base + (uint32_t)off, w);
                    }
                }
            }
            if (lane == 0)
                asm volatile("mbarrier.arrive.release.cluster.shared::cluster.b64 _, [%0];"
                             :: "r"(p_mbar) : "memory");
            BARN(5, 256);   // local head writes visible
            // wait for peer's head half
            {
                uint32_t done;
                do {
                    asm volatile(
                        "{\n\t.reg .pred p;\n\t"
                        "mbarrier.try_wait.parity.acquire.cluster.shared::cta.b64 p, [%1], %2, 0x989680;\n\t"
                        "selp.b32 %0, 1, 0, p;\n\t}"
                        : "=r"(done) : "r"(l_mbar), "r"(mph) : "memory");
                } while (!done);
            }
            mph ^= 1;

            // ---- memory module: 2 warps per local elem ----
            if (t < s_len[mge]) {
                const __half* Me = s_M + mel * (MEMN * WORDN);
                {
                    int rl = lane >> 3;
                    int cc = (lane & 7) * 16;
                    float2 kx[8];
                    #pragma unroll
                    for (int i = 0; i < 8; i++)
                        kx[i] = make_float2(s_key[mel][cc + 2 * i], s_key[mel][cc + 2 * i + 1]);
                    #pragma unroll 4
                    for (int mb = half * 64; mb < half * 64 + 64; mb += 4) {
                        int m = mb + rl;
                        const uint4* Mr = (const uint4*)(Me + m * WORDN + cc);
                        uint4 u0 = Mr[0];
                        uint4 u1 = Mr[1];
                        const __half2* p0 = (const __half2*)&u0;
                        const __half2* p1 = (const __half2*)&u1;
                        float2 d2 = make_float2(0.f, 0.f), n2 = make_float2(0.f, 0.f);
                        #pragma unroll
                        for (int q = 0; q < 4; q++) {
                            float2 f0 = __half22float2(p0[q]);
                            float2 f1 = __half22float2(p1[q]);
                            ffma2(d2, f0, kx[q]);
                            ffma2(n2, f0, f0);
                            ffma2(d2, f1, kx[4 + q]);
                            ffma2(n2, f1, f1);
                        }
                        float dot = d2.x + d2.y, nrm = n2.x + n2.y;
                        #pragma unroll
                        for (int s = 1; s < 8; s <<= 1) {
                            dot += __shfl_xor_sync(0xffffffffu, dot, s);
                            nrm += __shfl_xor_sync(0xffffffffu, nrm, s);
                        }
                        if ((lane & 7) == 0) s_w[mel][m] = __fdividef(dot, sqrt_fast(nrm) + EPSF);
                    }
                }
                BARN(1 + mel, 64);
                if (half == 0) {
                    float q0 = s_key[mel][lane];
                    float q1 = s_key[mel][lane + 32];
                    float q2 = s_key[mel][lane + 64];
                    float q3 = s_key[mel][lane + 96];
                    float ss = q0 * q0 + q1 * q1 + q2 * q2 + q3 * q3;
                    #pragma unroll
                    for (int s = 16; s; s >>= 1) ss += __shfl_xor_sync(0xffffffffu, ss, s);
                    float scale = __fdividef(s_beta[mel], sqrt_fast(ss) + EPSF);
                    float v0 = scale * s_w[mel][lane];
                    float v1 = scale * s_w[mel][lane + 32];
                    float v2 = scale * s_w[mel][lane + 64];
                    float v3 = scale * s_w[mel][lane + 96];
                    float mx = fmaxf(fmaxf(v0, v1), fmaxf(v2, v3));
                    #pragma unroll
                    for (int s = 16; s; s >>= 1) mx = fmaxf(mx, __shfl_xor_sync(0xffffffffu, mx, s));
                    v0 = __expf(v0 - mx); v1 = __expf(v1 - mx);
                    v2 = __expf(v2 - mx); v3 = __expf(v3 - mx);
                    float sum = v0 + v1 + v2 + v3;
                    #pragma unroll
                    for (int s = 16; s; s >>= 1) sum += __shfl_xor_sync(0xffffffffu, sum, s);
                    float inv = __fdividef(1.0f, sum);
                    s_w[mel][lane] = v0 * inv;
                    s_w[mel][lane + 32] = v1 * inv;
                    s_w[mel][lane + 64] = v2 * inv;
                    s_w[mel][lane + 96] = v3 * inv;
                }
                BARN(1 + mel, 64);
                {
                    __half* Mw = s_M + mel * (MEMN * WORDN) + lane * 4;
                    float4 e4 = *(const float4*)&s_e[mel][lane * 4];
                    float4 a4 = *(const float4*)&s_a[mel][lane * 4];
                    float2 en01 = make_float2(-e4.x, -e4.y), en23 = make_float2(-e4.z, -e4.w);
                    float2 a01 = make_float2(a4.x, a4.y),    a23 = make_float2(a4.z, a4.w);
                    float2 r01 = make_float2(0.f, 0.f), r23 = make_float2(0.f, 0.f);
                    #pragma unroll 8
                    for (int m = half * 64; m < half * 64 + 64; ++m) {
                        float wm = s_w[mel][m];
                        float2 wm2 = dup2(wm);
                        uint2 u = *(uint2*)(Mw + m * WORDN);
                        __half2* hp = (__half2*)&u;
                        float2 m01 = __half22float2(hp[0]);
                        float2 m23 = __half22float2(hp[1]);
                        ffma2(r01, wm2, m01);
                        ffma2(r23, wm2, m23);
                        float2 f01 = make_float2(1.f, 1.f), f23 = make_float2(1.f, 1.f);
                        ffma2(f01, wm2, en01);
                        ffma2(f23, wm2, en23);
                        float2 w01 = make_float2(0.f, 0.f), w23 = make_float2(0.f, 0.f);
                        ffma2(w01, wm2, a01);
                        ffma2(w23, wm2, a23);
                        ffma2(w01, m01, f01);
                        ffma2(w23, m23, f23);
                        hp[0] = __floats2half2_rn(w01.x, w01.y);
                        hp[1] = __floats2half2_rn(w23.x, w23.y);
                        *(uint2*)(Mw + m * WORDN) = u;
                    }
                    *(float4*)&s_racc[mel][half][lane * 4] = make_float4(r01.x, r01.y, r23.x, r23.y);
                }
                BARN(1 + mel, 64);
                {
                    int w = half * 32 + lane;
                    float s1 = s_racc[mel][0][w] + s_racc[mel][1][w];
                    s_read[mel][w] = s1;
                    __half h1 = __float2half(s1);
                    s_inh[mge * STRX + 64 + w] = h1;
                    stc_h(p_inh + (uint32_t)(mge * STRX + 64 + w) * 2u, h1);
                    int w2 = w + 64;
                    float s2 = s_racc[mel][0][w2] + s_racc[mel][1][w2];
                    s_read[mel][w2] = s2;
                    __half h2 = __float2half(s2);
                    s_inh[mge * STRX + 64 + w2] = h2;
                    stc_h(p_inh + (uint32_t)(mge * STRX + 64 + w2) * 2u, h2);
                }
            }
        }
        CL_SYNC();   // end of step: read rows visible in both CTAs
    }

    // ---- epilogue ----
    for (int q = tid; q < BN; q += 512) {
        int u = unsort_idxs[q];
        if (u >= b0blk && u < b0blk + 8) s_dst[u - b0blk] = q;
    }
    __syncthreads();
    if (khalf == 1) {
        #pragma unroll
        for (int c = 0; c < 4; ++c) {
            int jg = jgS + ((c & 2) ? 8 : 0);
            int ee = 2 * tig + (c & 1);
            out[(size_t)s_dst[ee] * CTRLN + jg] = hreg[c];
        }
    }
    {
        int el = tid >> 7, w = tid & 127;
        int ge = (int)rank * 4 + el;
        out[(size_t)BN * CTRLN + (size_t)s_dst[ge] * WORDN + w] = s_read[el][w];
    }
}

// ---------------- launch ----------------
extern "C" void kernel_launch(void* const* d_in, const int* in_sizes, int n_in,
                              void* d_out, int out_size) {
    const float* data        = (const float*)d_in[0];
    const int*   batch_sizes = (const int*)d_in[1];
    const int*   unsort      = (const int*)d_in[2];
    const float* W_ih        = (const float*)d_in[3];
    const float* b_ih        = (const float*)d_in[4];
    const float* W_hh        = (const float*)d_in[5];
    const float* b_hh        = (const float*)d_in[6];
    const float* W_key       = (const float*)d_in[7];
    const float* b_key       = (const float*)d_in[8];
    const float* W_beta      = (const float*)d_in[9];
    const float* b_beta      = (const float*)d_in[10];
    const float* W_erase     = (const float*)d_in[11];
    const float* b_erase     = (const float*)d_in[12];
    const float* W_add       = (const float*)d_in[13];
    const float* b_add       = (const float*)d_in[14];
    const float* M0          = (const float*)d_in[15];

    cudaFuncSetAttribute(ntm_main, cudaFuncAttributeMaxDynamicSharedMemorySize, SMEM_TOTAL);
    ntm_prep<<<256, 256>>>(W_ih, W_hh, W_key, W_beta, W_erase, W_add);
    ntm_main<<<128, 512, SMEM_TOTAL>>>(data, batch_sizes, unsort,
                                       b_ih, b_hh, b_key, b_beta, b_erase, b_add,
                                       M0, (float*)d_out);
}

// round 15
// speedup vs baseline: 1.0403x; 1.0097x over previous
#include <cuda_runtime.h>
#include <cuda_fp16.h>
#include <stdint.h>
#include <math.h>

#define CTRLN 256
#define WORDN 128
#define MEMN  128
#define DINN  64
#define BN    512
#define TN    512
#define EPSF  1e-6f

#define STRX 200   // s_inh row stride (halves)
#define STRH 264   // s_hHf row stride (halves)

// fragment-major fp16 weights
__device__ __half gA[16 * 3 * 28 * 256];   // GRU: [mpos][gate][ktile] x 256 halves/tile
__device__ __half gAH[32 * 16 * 256];      // head: [htile][ktile] x 256 halves/tile

// ---------------- helpers ----------------
__device__ __forceinline__ void ffma2(float2 &d, float2 a, float2 b) {
    unsigned long long &du = reinterpret_cast<unsigned long long &>(d);
    unsigned long long au = reinterpret_cast<unsigned long long &>(a);
    unsigned long long bu = reinterpret_cast<unsigned long long &>(b);
    asm("fma.rn.f32x2 %0, %1, %2, %0;" : "+l"(du) : "l"(au), "l"(bu));
}
__device__ __forceinline__ float2 dup2(float a) { return make_float2(a, a); }
__device__ __forceinline__ float sigf(float x) {
    return __fdividef(1.0f, 1.0f + __expf(-x));
}
__device__ __forceinline__ float tanhf_fast(float x) {
    float ax = fabsf(x);
    float t = __expf(-2.0f * ax);
    float r = (1.0f - t) * __fdividef(1.0f, 1.0f + t);
    return copysignf(r, x);
}
__device__ __forceinline__ float softplusf(float x) {
    return fmaxf(x, 0.0f) + log1pf(__expf(-fabsf(x)));
}
__device__ __forceinline__ float sqrt_fast(float x) {
    float xs = x + 1e-30f;
    return xs * rsqrtf(xs);
}
#define BARN(id, cnt) asm volatile("bar.sync %0, %1;" :: "r"(id), "r"(cnt) : "memory")
#define CL_SYNC() do { \
    asm volatile("barrier.cluster.arrive.aligned;" ::: "memory"); \
    asm volatile("barrier.cluster.wait.aligned;" ::: "memory"); \
} while (0)

__device__ __forceinline__ uint32_t ctarank() {
    uint32_t r; asm("mov.u32 %0, %%cluster_ctarank;" : "=r"(r)); return r;
}
__device__ __forceinline__ uint32_t mapa_u32(uint32_t a, uint32_t r) {
    uint32_t d; asm("mapa.shared::cluster.u32 %0, %1, %2;" : "=r"(d) : "r"(a), "r"(r)); return d;
}
__device__ __forceinline__ void stc_h(uint32_t a, __half v) {
    asm volatile("st.shared::cluster.b16 [%0], %1;" :: "r"(a), "h"(__half_as_ushort(v)) : "memory");
}
__device__ __forceinline__ void stc_f(uint32_t a, float v) {
    asm volatile("st.shared::cluster.f32 [%0], %1;" :: "r"(a), "f"(v) : "memory");
}
__device__ __forceinline__ void mb_arrive_peer(uint32_t a) {
    asm volatile("mbarrier.arrive.release.cluster.shared::cluster.b64 _, [%0];"
                 :: "r"(a) : "memory");
}
__device__ __forceinline__ void mb_wait(uint32_t a, uint32_t ph) {
    uint32_t done;
    do {
        asm volatile(
            "{\n\t.reg .pred p;\n\t"
            "mbarrier.try_wait.parity.acquire.cluster.shared::cta.b64 p, [%1], %2, 0x989680;\n\t"
            "selp.b32 %0, 1, 0, p;\n\t}"
            : "=r"(done) : "r"(a), "r"(ph) : "memory");
    } while (!done);
}

#define MMA(C, A, B0, B1) \
    asm volatile("mma.sync.aligned.m16n8k16.row.col.f32.f16.f16.f32 " \
        "{%0,%1,%2,%3},{%4,%5,%6,%7},{%8,%9},{%0,%1,%2,%3};" \
        : "+f"((C)[0]), "+f"((C)[1]), "+f"((C)[2]), "+f"((C)[3]) \
        : "r"((A).x), "r"((A).y), "r"((A).z), "r"((A).w), "r"(B0), "r"(B1))

// ---------------- K0: repack weights to fragment-major fp16 ----------------
__global__ void ntm_prep(const float* __restrict__ W_ih, const float* __restrict__ W_hh,
                         const float* __restrict__ W_key, const float* __restrict__ W_beta,
                         const float* __restrict__ W_erase, const float* __restrict__ W_add) {
    int stride = gridDim.x * blockDim.x;
    int idx0 = blockIdx.x * blockDim.x + threadIdx.x;
    for (int i = idx0; i < 16 * 3 * 28 * 256; i += stride) {
        int tile = i >> 8, rem = i & 255;
        int lane = rem >> 3, p = rem & 7;
        int gid = lane >> 2, tig = lane & 3;
        int reg = p >> 1, w = p & 1;
        int r = gid + (reg & 1) * 8;
        int k = 2 * tig + (reg >> 1) * 8 + w;
        int mt = tile / 84, g = (tile / 28) % 3, kt = tile % 28;
        int o = g * 256 + mt * 16 + r;
        float v = (kt < 12) ? W_ih[o * 192 + kt * 16 + k]
                            : W_hh[o * 256 + (kt - 12) * 16 + k];
        gA[i] = __float2half(v);
    }
    for (int i = idx0; i < 32 * 16 * 256; i += stride) {
        int tile = i >> 8, rem = i & 255;
        int lane = rem >> 3, p = rem & 7;
        int gid = lane >> 2, tig = lane & 3;
        int reg = p >> 1, w = p & 1;
        int r = gid + (reg & 1) * 8;
        int k = 2 * tig + (reg >> 1) * 8 + w;
        int ht = tile / 16, kt = tile % 16;
        int o = ht * 16 + r;
        int kk = kt * 16 + k;
        float v = 0.0f;
        if (o < 128)       v = W_key[o * 256 + kk];
        else if (o < 256)  v = W_erase[(o - 128) * 256 + kk];
        else if (o < 384)  v = W_add[(o - 256) * 256 + kk];
        else if (o == 384) v = W_beta[kk];
        gAH[i] = __float2half(v);
    }
}

// SMEM layout offsets (bytes)
#define OFF_INH   0
#define OFF_HHF   3200
#define OFF_RED   7424
#define OFF_REDS  23808
#define OFF_KEY   36096
#define OFF_E     38144
#define OFF_A     40192
#define OFF_W     42240
#define OFF_RACC  44288
#define OFF_READ  52480
#define OFF_BETA  54528
#define OFF_LEN   54544
#define OFF_DST   54576
#define OFF_MBAR  54608
#define OFF_M     54656
#define SMEM_TOTAL (54656 + 4 * MEMN * WORDN * 2)   // 185728 bytes

// ---------------- K1: cluster-of-2 tensor-core kernel, mbarrier sync ----------------
__global__ __launch_bounds__(512, 1) __cluster_dims__(2, 1, 1)
void ntm_main(const float* __restrict__ data, const int* __restrict__ batch_sizes,
              const int* __restrict__ unsort_idxs,
              const float* __restrict__ b_ih, const float* __restrict__ b_hh,
              const float* __restrict__ b_key, const float* __restrict__ b_beta,
              const float* __restrict__ b_erase, const float* __restrict__ b_add,
              const float* __restrict__ M0, float* __restrict__ out) {
    extern __shared__ __align__(16) unsigned char dsm[];
    __half* s_inh           = (__half*)(dsm + OFF_INH);   // [8 elem][STRX]
    __half* s_hHf           = (__half*)(dsm + OFF_HHF);   // [8 elem][STRH]
    float*  red             = (float*)(dsm + OFF_RED);    // pipe partials [4][128 jl][8 e]
    float*  redS            = (float*)(dsm + OFF_REDS);   // serial khalf0 partials [3][128][8]
    float (*s_key)[128]     = (float(*)[128])(dsm + OFF_KEY);
    float (*s_e)[128]       = (float(*)[128])(dsm + OFF_E);
    float (*s_a)[128]       = (float(*)[128])(dsm + OFF_A);
    float (*s_w)[128]       = (float(*)[128])(dsm + OFF_W);
    float (*s_racc)[4][128] = (float(*)[4][128])(dsm + OFF_RACC);  // [4 el][4 qt][128]
    float (*s_read)[128]    = (float(*)[128])(dsm + OFF_READ);
    float* s_beta           = (float*)(dsm + OFF_BETA);
    int*   s_len            = (int*)(dsm + OFF_LEN);
    int*   s_dst            = (int*)(dsm + OFF_DST);
    __half* s_M             = (__half*)(dsm + OFF_M);     // [4 local el][128][128]

    const int tid = threadIdx.x;
    const int lane = tid & 31;
    const int warp = tid >> 5;
    const int gid = lane >> 2, tig = lane & 3;
    const uint32_t rank = ctarank();
    const uint32_t peer = rank ^ 1u;
    const int b0blk = (blockIdx.x >> 1) * 8;

    const uint32_t l_base = (uint32_t)__cvta_generic_to_shared(dsm);
    const uint32_t p_base = mapa_u32(l_base, peer);
    const uint32_t l_mbH = l_base + OFF_MBAR,      p_mbH = p_base + OFF_MBAR;
    const uint32_t l_mbD = l_base + OFF_MBAR + 8,  p_mbD = p_base + OFF_MBAR + 8;
    const uint32_t l_mbR = l_base + OFF_MBAR + 16, p_mbR = p_base + OFF_MBAR + 16;
    const uint32_t p_inh  = p_base + OFF_INH;
    const uint32_t p_hHf  = p_base + OFF_HHF;

    // ---- active lengths ----
    if (warp < 8) {
        int e = warp, cnt = 0;
        for (int t = lane; t < TN; t += 32) cnt += (batch_sizes[t] > (b0blk + e)) ? 1 : 0;
        #pragma unroll
        for (int s = 16; s; s >>= 1) cnt += __shfl_xor_sync(0xffffffffu, cnt, s);
        if (lane == 0) s_len[e] = cnt;
    }
    // ---- init M ----
    for (int i = tid; i < (MEMN * WORDN) / 2; i += 512) {
        float2 f = ((const float2*)M0)[i];
        __half2 h = __floats2half2_rn(f.x, f.y);
        #pragma unroll
        for (int el = 0; el < 4; el++)
            ((__half2*)s_M)[el * ((MEMN * WORDN) / 2) + i] = h;
    }
    for (int i = tid; i < 8 * STRX; i += 512) s_inh[i] = __float2half(0.0f);
    for (int i = tid; i < 8 * STRH; i += 512) s_hHf[i] = __float2half(0.0f);
    if (tid == 0) {
        asm volatile("mbarrier.init.shared.b64 [%0], %1;" :: "r"(l_mbH), "r"(256) : "memory");
        asm volatile("mbarrier.init.shared.b64 [%0], %1;" :: "r"(l_mbD), "r"(256) : "memory");
        asm volatile("mbarrier.init.shared.b64 [%0], %1;" :: "r"(l_mbR), "r"(512) : "memory");
    }

    // ---- per-lane constants ----
    const int mpS = warp >> 1;
    const int khalf = warp & 1;
    const int mpgS = (int)rank * 8 + mpS;
    const int jlS = mpS * 16 + gid;
    const int jgS = (int)rank * 128 + jlS;
    const float bR0 = b_ih[jgS] + b_hh[jgS],             bR1 = b_ih[jgS + 8] + b_hh[jgS + 8];
    const float bZ0 = b_ih[256 + jgS] + b_hh[256 + jgS], bZ1 = b_ih[256 + jgS + 8] + b_hh[256 + jgS + 8];
    const float bNi0 = b_ih[512 + jgS],                  bNi1 = b_ih[512 + jgS + 8];
    const float bNh0 = b_hh[512 + jgS],                  bNh1 = b_hh[512 + jgS + 8];
    float bHv[4];
    if (warp < 8) {
        #pragma unroll
        for (int tt = 0; tt < 2; tt++) {
            int ht = (int)rank * 16 + warp * 2 + tt;
            #pragma unroll
            for (int rr = 0; rr < 2; rr++) {
                int oo = ht * 16 + gid + rr * 8;
                float v = (oo < 128) ? b_key[oo]
                        : (oo < 256) ? b_erase[oo - 128]
                        : (oo < 384) ? b_add[oo - 256]
                        : ((oo == 384) ? b_beta[0] : 0.0f);
                bHv[tt * 2 + rr] = v;
            }
        }
    }
    float hreg[4] = {0.f, 0.f, 0.f, 0.f};

    // module/pass2 group roles: 4 warps per local elem {2el, 2el+1, 8+2el, 9+2el}
    const int el_g = (warp < 8) ? (warp >> 1) : ((warp - 8) >> 1);
    const int qt_g = (warp < 8) ? (warp & 1) : (2 + ((warp - 8) & 1));
    const int ge_g = (int)rank * 4 + el_g;
    const int mel = warp >> 1;       // module warps 0-7
    const int half = warp & 1;

    // ---- x prefetch ----
    const int xe = tid >> 6, xd = tid & 63;
    float xreg = data[((size_t)0 * BN + (b0blk + xe)) * DINN + xd];
    __syncthreads();

    const int Le0 = s_len[2 * tig], Le1 = s_len[2 * tig + 1];
    int Tmax = 0;
    #pragma unroll
    for (int e = 0; e < 8; e++) Tmax = max(Tmax, s_len[e]);

    s_inh[xe * STRX + xd] = __float2half(xreg);
    xreg = data[((size_t)1 * BN + (b0blk + xe)) * DINN + xd];
    __syncthreads();

    // ---- prologue pipe: P_0 = gi_x(x_0) (h=0) ----
    if (warp >= 8) {
        const int mpP = warp - 8;
        const int mpgP = (int)rank * 8 + mpP;
        const int jlP = mpP * 16 + gid;
        float C[4][4];
        #pragma unroll
        for (int a = 0; a < 4; a++)
            #pragma unroll
            for (int c = 0; c < 4; c++) C[a][c] = 0.0f;
        const uint4* A = (const uint4*)gA;
        #pragma unroll 2
        for (int kt = 0; kt < 4; ++kt) {
            uint32_t b0 = *(const uint32_t*)(s_inh + gid * STRX + kt * 16 + 2 * tig);
            uint32_t b1 = *(const uint32_t*)(s_inh + gid * STRX + kt * 16 + 2 * tig + 8);
            uint4 ar = __ldg(&A[(size_t)((mpgP * 3 + 0) * 28 + kt) * 32 + lane]);
            uint4 az = __ldg(&A[(size_t)((mpgP * 3 + 1) * 28 + kt) * 32 + lane]);
            uint4 an = __ldg(&A[(size_t)((mpgP * 3 + 2) * 28 + kt) * 32 + lane]);
            MMA(C[0], ar, b0, b1); MMA(C[1], az, b0, b1); MMA(C[2], an, b0, b1);
        }
        #pragma unroll
        for (int a = 0; a < 4; a++) {
            *(float2*)&red[(a * 128 + jlP) * 8 + 2 * tig] = make_float2(C[a][0], C[a][1]);
            *(float2*)&red[(a * 128 + jlP + 8) * 8 + 2 * tig] = make_float2(C[a][2], C[a][3]);
        }
    }
    __syncthreads();
    CL_SYNC();   // mbarrier init + prologue visible cluster-wide

    for (int t = 0; t < Tmax; ++t) {
        // wait peer read_{t-1}
        if (t > 0) mb_wait(l_mbR, (t & 1) ^ 1);

        // ======== SERIAL: gi_read mma, split-k (4 kt per warp) ========
        float Cr[4] = {0, 0, 0, 0}, Cz[4] = {0, 0, 0, 0}, Cni[4] = {0, 0, 0, 0};
        {
            const uint4* A = (const uint4*)gA;
            const int ktb = 4 + 4 * khalf;
            #pragma unroll
            for (int kt = ktb; kt < ktb + 4; ++kt) {
                uint32_t b0 = *(const uint32_t*)(s_inh + gid * STRX + kt * 16 + 2 * tig);
                uint32_t b1 = *(const uint32_t*)(s_inh + gid * STRX + kt * 16 + 2 * tig + 8);
                uint4 ar = __ldg(&A[(size_t)((mpgS * 3 + 0) * 28 + kt) * 32 + lane]);
                uint4 az = __ldg(&A[(size_t)((mpgS * 3 + 1) * 28 + kt) * 32 + lane]);
                uint4 an = __ldg(&A[(size_t)((mpgS * 3 + 2) * 28 + kt) * 32 + lane]);
                MMA(Cr, ar, b0, b1);
                MMA(Cz, az, b0, b1);
                MMA(Cni, an, b0, b1);
            }
        }
        if (khalf == 0) {
            #pragma unroll
            for (int rr = 0; rr < 2; rr++) {
                int jl = jlS + rr * 8;
                *(float2*)&redS[(0 * 128 + jl) * 8 + 2 * tig] = make_float2(Cr[2 * rr], Cr[2 * rr + 1]);
                *(float2*)&redS[(1 * 128 + jl) * 8 + 2 * tig] = make_float2(Cz[2 * rr], Cz[2 * rr + 1]);
                *(float2*)&redS[(2 * 128 + jl) * 8 + 2 * tig] = make_float2(Cni[2 * rr], Cni[2 * rr + 1]);
            }
        }
        __syncthreads();   // B1

        // ---- gates (odd warps) + x-store (all) ----
        if (khalf == 1) {
            #pragma unroll
            for (int c = 0; c < 4; ++c) {
                int rr = (c >> 1) & 1;
                int jl = jlS + rr * 8;
                int jg = jgS + rr * 8;
                int ee = 2 * tig + (c & 1);
                int Lc = (c & 1) ? Le1 : Le0;
                float rp = Cr[c]  + redS[(0 * 128 + jl) * 8 + ee] + red[(0 * 128 + jl) * 8 + ee] + (rr ? bR1 : bR0);
                float zp = Cz[c]  + redS[(1 * 128 + jl) * 8 + ee] + red[(1 * 128 + jl) * 8 + ee] + (rr ? bZ1 : bZ0);
                float np = Cni[c] + redS[(2 * 128 + jl) * 8 + ee] + red[(2 * 128 + jl) * 8 + ee] + (rr ? bNi1 : bNi0);
                float nh = red[(3 * 128 + jl) * 8 + ee] + (rr ? bNh1 : bNh0);
                float r = sigf(rp);
                float z = sigf(zp);
                float n = tanhf_fast(np + r * nh);
                float h = (1.0f - z) * n + z * hreg[c];
                if (t < Lc) hreg[c] = h;
                __half hh = __float2half(hreg[c]);
                s_hHf[ee * STRH + jg] = hh;
                stc_h(p_hHf + (uint32_t)(ee * STRH + jg) * 2u, hh);
            }
            mb_arrive_peer(p_mbH);
        }
        s_inh[xe * STRX + xd] = __float2half(xreg);
        {
            int tn = min(t + 2, TN - 1);
            xreg = data[((size_t)tn * BN + (b0blk + xe)) * DINN + xd];
        }
        __syncthreads();        // B2: local h + local x visible
        mb_wait(l_mbH, t & 1);  // peer h visible

        // ======== PARALLEL ========
        if (warp >= 8) {
            // pipe: P_{t+1} = gh(h_t) + gi_x(x_{t+1})
            const int mpP = warp - 8;
            const int mpgP = (int)rank * 8 + mpP;
            const int jlP = mpP * 16 + gid;
            float C[4][4];
            #pragma unroll
            for (int a = 0; a < 4; a++)
                #pragma unroll
                for (int c = 0; c < 4; c++) C[a][c] = 0.0f;
            const uint4* A = (const uint4*)gA;
            #pragma unroll 2
            for (int kt = 0; kt < 4; ++kt) {
                uint32_t b0 = *(const uint32_t*)(s_inh + gid * STRX + kt * 16 + 2 * tig);
                uint32_t b1 = *(const uint32_t*)(s_inh + gid * STRX + kt * 16 + 2 * tig + 8);
                uint4 ar = __ldg(&A[(size_t)((mpgP * 3 + 0) * 28 + kt) * 32 + lane]);
                uint4 az = __ldg(&A[(size_t)((mpgP * 3 + 1) * 28 + kt) * 32 + lane]);
                uint4 an = __ldg(&A[(size_t)((mpgP * 3 + 2) * 28 + kt) * 32 + lane]);
                MMA(C[0], ar, b0, b1); MMA(C[1], az, b0, b1); MMA(C[2], an, b0, b1);
            }
            #pragma unroll 2
            for (int kt = 0; kt < 16; ++kt) {
                uint32_t b0 = *(const uint32_t*)(s_hHf + gid * STRH + kt * 16 + 2 * tig);
                uint32_t b1 = *(const uint32_t*)(s_hHf + gid * STRH + kt * 16 + 2 * tig + 8);
                uint4 ar = __ldg(&A[(size_t)((mpgP * 3 + 0) * 28 + 12 + kt) * 32 + lane]);
                uint4 az = __ldg(&A[(size_t)((mpgP * 3 + 1) * 28 + 12 + kt) * 32 + lane]);
                uint4 an = __ldg(&A[(size_t)((mpgP * 3 + 2) * 28 + 12 + kt) * 32 + lane]);
                MMA(C[0], ar, b0, b1); MMA(C[1], az, b0, b1); MMA(C[3], an, b0, b1);
            }
            #pragma unroll
            for (int a = 0; a < 4; a++) {
                *(float2*)&red[(a * 128 + jlP) * 8 + 2 * tig] = make_float2(C[a][0], C[a][1]);
                *(float2*)&red[(a * 128 + jlP + 8) * 8 + 2 * tig] = make_float2(C[a][2], C[a][3]);
            }
        } else {
            // ---- head mma: 2 h-tiles per warp ----
            float CH[2][4];
            #pragma unroll
            for (int tt = 0; tt < 2; tt++)
                #pragma unroll
                for (int c = 0; c < 4; c++) CH[tt][c] = 0.0f;
            const uint4* AH = (const uint4*)gAH;
            const int htb = (int)rank * 16 + warp * 2;
            #pragma unroll 2
            for (int kt = 0; kt < 16; ++kt) {
                uint32_t b0 = *(const uint32_t*)(s_hHf + gid * STRH + kt * 16 + 2 * tig);
                uint32_t b1 = *(const uint32_t*)(s_hHf + gid * STRH + kt * 16 + 2 * tig + 8);
                #pragma unroll
                for (int tt = 0; tt < 2; tt++) {
                    uint4 a = __ldg(&AH[(size_t)((htb + tt) * 16 + kt) * 32 + lane]);
                    MMA(CH[tt], a, b0, b1);
                }
            }
            #pragma unroll
            for (int tt = 0; tt < 2; tt++) {
                #pragma unroll
                for (int c = 0; c < 4; c++) {
                    int o = (htb + tt) * 16 + gid + ((c >> 1) << 3);
                    int e = 2 * tig + (c & 1);
                    float v = CH[tt][c] + bHv[tt * 2 + (c >> 1)];
                    if (o <= 384) {
                        float w;
                        int off;
                        if (o < 128)      { w = tanhf_fast(v); off = OFF_KEY + ((e & 3) * 128 + o) * 4; }
                        else if (o < 256) { w = sigf(v);       off = OFF_E + ((e & 3) * 128 + o - 128) * 4; }
                        else if (o < 384) { w = v;             off = OFF_A + ((e & 3) * 128 + o - 256) * 4; }
                        else              { w = softplusf(v);  off = OFF_BETA + (e & 3) * 4; }
                        if ((e >> 2) == (int)rank) *(float*)(dsm + off) = w;
                        else stc_f(p_base + (uint32_t)off, w);
                    }
                }
            }
            mb_arrive_peer(p_mbD);
            BARN(5, 256);            // local head writes visible
            mb_wait(l_mbD, t & 1);   // peer head half visible

            // ---- module pass1 + softmax (2 warps per local elem) ----
            if (t < s_len[ge_g]) {
                const __half* Me = s_M + mel * (MEMN * WORDN);
                {
                    int rl = lane >> 3;
                    int cc = (lane & 7) * 16;
                    float2 kx[8];
                    #pragma unroll
                    for (int i = 0; i < 8; i++)
                        kx[i] = make_float2(s_key[mel][cc + 2 * i], s_key[mel][cc + 2 * i + 1]);
                    #pragma unroll 4
                    for (int mb = half * 64; mb < half * 64 + 64; mb += 4) {
                        int m = mb + rl;
                        const uint4* Mr = (const uint4*)(Me + m * WORDN + cc);
                        uint4 u0 = Mr[0];
                        uint4 u1 = Mr[1];
                        const __half2* p0 = (const __half2*)&u0;
                        const __half2* p1 = (const __half2*)&u1;
                        float2 d2 = make_float2(0.f, 0.f), n2 = make_float2(0.f, 0.f);
                        #pragma unroll
                        for (int q = 0; q < 4; q++) {
                            float2 f0 = __half22float2(p0[q]);
                            float2 f1 = __half22float2(p1[q]);
                            ffma2(d2, f0, kx[q]);
                            ffma2(n2, f0, f0);
                            ffma2(d2, f1, kx[4 + q]);
                            ffma2(n2, f1, f1);
                        }
                        float dot = d2.x + d2.y, nrm = n2.x + n2.y;
                        #pragma unroll
                        for (int s = 1; s < 8; s <<= 1) {
                            dot += __shfl_xor_sync(0xffffffffu, dot, s);
                            nrm += __shfl_xor_sync(0xffffffffu, nrm, s);
                        }
                        if ((lane & 7) == 0) s_w[mel][m] = __fdividef(dot, sqrt_fast(nrm) + EPSF);
                    }
                }
                BARN(1 + mel, 64);
                if (half == 0) {
                    float q0 = s_key[mel][lane];
                    float q1 = s_key[mel][lane + 32];
                    float q2 = s_key[mel][lane + 64];
                    float q3 = s_key[mel][lane + 96];
                    float ss = q0 * q0 + q1 * q1 + q2 * q2 + q3 * q3;
                    #pragma unroll
                    for (int s = 16; s; s >>= 1) ss += __shfl_xor_sync(0xffffffffu, ss, s);
                    float scale = __fdividef(s_beta[mel], sqrt_fast(ss) + EPSF);
                    float v0 = scale * s_w[mel][lane];
                    float v1 = scale * s_w[mel][lane + 32];
                    float v2 = scale * s_w[mel][lane + 64];
                    float v3 = scale * s_w[mel][lane + 96];
                    float mx = fmaxf(fmaxf(v0, v1), fmaxf(v2, v3));
                    #pragma unroll
                    for (int s = 16; s; s >>= 1) mx = fmaxf(mx, __shfl_xor_sync(0xffffffffu, mx, s));
                    v0 = __expf(v0 - mx); v1 = __expf(v1 - mx);
                    v2 = __expf(v2 - mx); v3 = __expf(v3 - mx);
                    float sum = v0 + v1 + v2 + v3;
                    #pragma unroll
                    for (int s = 16; s; s >>= 1) sum += __shfl_xor_sync(0xffffffffu, sum, s);
                    float inv = __fdividef(1.0f, sum);
                    s_w[mel][lane] = v0 * inv;
                    s_w[mel][lane + 32] = v1 * inv;
                    s_w[mel][lane + 64] = v2 * inv;
                    s_w[mel][lane + 96] = v3 * inv;
                }
                BARN(1 + mel, 64);
            }
        }

        // ======== PASS2: joined, 4 warps per local elem ========
        if (t < s_len[ge_g]) {
            BARN(6 + el_g, 128);   // join: s_w/s_e/s_a ready, pipe partials written
            {
                __half* Mw = s_M + el_g * (MEMN * WORDN) + lane * 4;
                float4 e4 = *(const float4*)&s_e[el_g][lane * 4];
                float4 a4 = *(const float4*)&s_a[el_g][lane * 4];
                float2 en01 = make_float2(-e4.x, -e4.y), en23 = make_float2(-e4.z, -e4.w);
                float2 a01 = make_float2(a4.x, a4.y),    a23 = make_float2(a4.z, a4.w);
                float2 r01 = make_float2(0.f, 0.f), r23 = make_float2(0.f, 0.f);
                #pragma unroll 8
                for (int m = qt_g * 32; m < qt_g * 32 + 32; ++m) {
                    float wm = s_w[el_g][m];
                    float2 wm2 = dup2(wm);
                    uint2 u = *(uint2*)(Mw + m * WORDN);
                    __half2* hp = (__half2*)&u;
                    float2 m01 = __half22float2(hp[0]);
                    float2 m23 = __half22float2(hp[1]);
                    ffma2(r01, wm2, m01);
                    ffma2(r23, wm2, m23);
                    float2 f01 = make_float2(1.f, 1.f), f23 = make_float2(1.f, 1.f);
                    ffma2(f01, wm2, en01);
                    ffma2(f23, wm2, en23);
                    float2 w01 = make_float2(0.f, 0.f), w23 = make_float2(0.f, 0.f);
                    ffma2(w01, wm2, a01);
                    ffma2(w23, wm2, a23);
                    ffma2(w01, m01, f01);
                    ffma2(w23, m23, f23);
                    hp[0] = __floats2half2_rn(w01.x, w01.y);
                    hp[1] = __floats2half2_rn(w23.x, w23.y);
                    *(uint2*)(Mw + m * WORDN) = u;
                }
                *(float4*)&s_racc[el_g][qt_g][lane * 4] = make_float4(r01.x, r01.y, r23.x, r23.y);
            }
            BARN(6 + el_g, 128);
            // combine quarters: each warp handles 32 read positions
            {
                int w = qt_g * 32 + lane;
                float s1 = (s_racc[el_g][0][w] + s_racc[el_g][1][w])
                         + (s_racc[el_g][2][w] + s_racc[el_g][3][w]);
                s_read[el_g][w] = s1;
                __half h1 = __float2half(s1);
                s_inh[ge_g * STRX + 64 + w] = h1;
                stc_h(p_inh + (uint32_t)(ge_g * STRX + 64 + w) * 2u, h1);
            }
        }
        mb_arrive_peer(p_mbR);   // unconditional (all 16 warps, all lanes)
        __syncthreads();         // loop-end: local read rows + red partials visible
    }

    // ---- epilogue ----
    CL_SYNC();   // no peer DSMEM writes in flight at teardown
    for (int q = tid; q < BN; q += 512) {
        int u = unsort_idxs[q];
        if (u >= b0blk && u < b0blk + 8) s_dst[u - b0blk] = q;
    }
    __syncthreads();
    if (khalf == 1) {
        #pragma unroll
        for (int c = 0; c < 4; ++c) {
            int jg = jgS + ((c & 2) ? 8 : 0);
            int ee = 2 * tig + (c & 1);
            out[(size_t)s_dst[ee] * CTRLN + jg] = hreg[c];
        }
    }
    {
        int el = tid >> 7, w = tid & 127;
        int ge = (int)rank * 4 + el;
        out[(size_t)BN * CTRLN + (size_t)s_dst[ge] * WORDN + w] = s_read[el][w];
    }
}

// ---------------- launch ----------------
extern "C" void kernel_launch(void* const* d_in, const int* in_sizes, int n_in,
                              void* d_out, int out_size) {
    const float* data        = (const float*)d_in[0];
    const int*   batch_sizes = (const int*)d_in[1];
    const int*   unsort      = (const int*)d_in[2];
    const float* W_ih        = (const float*)d_in[3];
    const float* b_ih        = (const float*)d_in[4];
    const float* W_hh        = (const float*)d_in[5];
    const float* b_hh        = (const float*)d_in[6];
    const float* W_key       = (const float*)d_in[7];
    const float* b_key       = (const float*)d_in[8];
    const float* W_beta      = (const float*)d_in[9];
    const float* b_beta      = (const float*)d_in[10];
    const float* W_erase     = (const float*)d_in[11];
    const float* b_erase     = (const float*)d_in[12];
    const float* W_add       = (const float*)d_in[13];
    const float* b_add       = (const float*)d_in[14];
    const float* M0          = (const float*)d_in[15];

    cudaFuncSetAttribute(ntm_main, cudaFuncAttributeMaxDynamicSharedMemorySize, SMEM_TOTAL);
    ntm_prep<<<256, 256>>>(W_ih, W_hh, W_key, W_beta, W_erase, W_add);
    ntm_main<<<128, 512, SMEM_TOTAL>>>(data, batch_sizes, unsort,
                                       b_ih, b_hh, b_key, b_beta, b_erase, b_add,
                                       M0, (float*)d_out);
}

// round 16
// speedup vs baseline: 1.0861x; 1.0440x over previous
#include <cuda_runtime.h>
#include <cuda_fp16.h>
#include <stdint.h>
#include <math.h>

#define CTRLN 256
#define WORDN 128
#define MEMN  128
#define DINN  64
#define BN    512
#define TN    512
#define EPSF  1e-6f

#define STRX 200   // s_inh row stride (halves)
#define STRH 264   // s_hHf row stride (halves)

// fragment-major fp16 weights
__device__ __half gA[16 * 3 * 28 * 256];   // GRU: [mpos][gate][ktile] x 256 halves/tile
__device__ __half gAH[32 * 16 * 256];      // head: [htile][ktile] x 256 halves/tile

// ---------------- helpers ----------------
__device__ __forceinline__ void ffma2(float2 &d, float2 a, float2 b) {
    unsigned long long &du = reinterpret_cast<unsigned long long &>(d);
    unsigned long long au = reinterpret_cast<unsigned long long &>(a);
    unsigned long long bu = reinterpret_cast<unsigned long long &>(b);
    asm("fma.rn.f32x2 %0, %1, %2, %0;" : "+l"(du) : "l"(au), "l"(bu));
}
__device__ __forceinline__ float2 dup2(float a) { return make_float2(a, a); }
__device__ __forceinline__ float sigf(float x) {
    return __fdividef(1.0f, 1.0f + __expf(-x));
}
__device__ __forceinline__ float tanhf_fast(float x) {
    float ax = fabsf(x);
    float t = __expf(-2.0f * ax);
    float r = (1.0f - t) * __fdividef(1.0f, 1.0f + t);
    return copysignf(r, x);
}
__device__ __forceinline__ float softplusf(float x) {
    return fmaxf(x, 0.0f) + log1pf(__expf(-fabsf(x)));
}
__device__ __forceinline__ float sqrt_fast(float x) {
    float xs = x + 1e-30f;
    return xs * rsqrtf(xs);
}
#define BARN(id, cnt) asm volatile("bar.sync %0, %1;" :: "r"(id), "r"(cnt) : "memory")
#define CL_SYNC() do { \
    asm volatile("barrier.cluster.arrive.aligned;" ::: "memory"); \
    asm volatile("barrier.cluster.wait.aligned;" ::: "memory"); \
} while (0)

__device__ __forceinline__ uint32_t ctarank() {
    uint32_t r; asm("mov.u32 %0, %%cluster_ctarank;" : "=r"(r)); return r;
}
__device__ __forceinline__ uint32_t mapa_u32(uint32_t a, uint32_t r) {
    uint32_t d; asm("mapa.shared::cluster.u32 %0, %1, %2;" : "=r"(d) : "r"(a), "r"(r)); return d;
}
__device__ __forceinline__ void stc_h(uint32_t a, __half v) {
    asm volatile("st.shared::cluster.b16 [%0], %1;" :: "r"(a), "h"(__half_as_ushort(v)) : "memory");
}
__device__ __forceinline__ void stc_f(uint32_t a, float v) {
    asm volatile("st.shared::cluster.f32 [%0], %1;" :: "r"(a), "f"(v) : "memory");
}
__device__ __forceinline__ void mb_arrive_peer(uint32_t a) {
    asm volatile("mbarrier.arrive.release.cluster.shared::cluster.b64 _, [%0];"
                 :: "r"(a) : "memory");
}
__device__ __forceinline__ void mb_wait(uint32_t a, uint32_t ph) {
    uint32_t done;
    do {
        asm volatile(
            "{\n\t.reg .pred p;\n\t"
            "mbarrier.try_wait.parity.acquire.cluster.shared::cta.b64 p, [%1], %2, 0x989680;\n\t"
            "selp.b32 %0, 1, 0, p;\n\t}"
            : "=r"(done) : "r"(a), "r"(ph) : "memory");
    } while (!done);
}

#define MMA(C, A, B0, B1) \
    asm volatile("mma.sync.aligned.m16n8k16.row.col.f32.f16.f16.f32 " \
        "{%0,%1,%2,%3},{%4,%5,%6,%7},{%8,%9},{%0,%1,%2,%3};" \
        : "+f"((C)[0]), "+f"((C)[1]), "+f"((C)[2]), "+f"((C)[3]) \
        : "r"((A).x), "r"((A).y), "r"((A).z), "r"((A).w), "r"(B0), "r"(B1))

// ---------------- K0: repack weights to fragment-major fp16 ----------------
__global__ void ntm_prep(const float* __restrict__ W_ih, const float* __restrict__ W_hh,
                         const float* __restrict__ W_key, const float* __restrict__ W_beta,
                         const float* __restrict__ W_erase, const float* __restrict__ W_add) {
    int stride = gridDim.x * blockDim.x;
    int idx0 = blockIdx.x * blockDim.x + threadIdx.x;
    for (int i = idx0; i < 16 * 3 * 28 * 256; i += stride) {
        int tile = i >> 8, rem = i & 255;
        int lane = rem >> 3, p = rem & 7;
        int gid = lane >> 2, tig = lane & 3;
        int reg = p >> 1, w = p & 1;
        int r = gid + (reg & 1) * 8;
        int k = 2 * tig + (reg >> 1) * 8 + w;
        int mt = tile / 84, g = (tile / 28) % 3, kt = tile % 28;
        int o = g * 256 + mt * 16 + r;
        float v = (kt < 12) ? W_ih[o * 192 + kt * 16 + k]
                            : W_hh[o * 256 + (kt - 12) * 16 + k];
        gA[i] = __float2half(v);
    }
    for (int i = idx0; i < 32 * 16 * 256; i += stride) {
        int tile = i >> 8, rem = i & 255;
        int lane = rem >> 3, p = rem & 7;
        int gid = lane >> 2, tig = lane & 3;
        int reg = p >> 1, w = p & 1;
        int r = gid + (reg & 1) * 8;
        int k = 2 * tig + (reg >> 1) * 8 + w;
        int ht = tile / 16, kt = tile % 16;
        int o = ht * 16 + r;
        int kk = kt * 16 + k;
        float v = 0.0f;
        if (o < 128)       v = W_key[o * 256 + kk];
        else if (o < 256)  v = W_erase[(o - 128) * 256 + kk];
        else if (o < 384)  v = W_add[(o - 256) * 256 + kk];
        else if (o == 384) v = W_beta[kk];
        gAH[i] = __float2half(v);
    }
}

// SMEM layout offsets (bytes)
#define OFF_INH   0
#define OFF_HHF   3200
#define OFF_RED   7424
#define OFF_REDS  23808
#define OFF_KEY   36096
#define OFF_E     38144
#define OFF_A     40192
#define OFF_W     42240
#define OFF_RACC  44288
#define OFF_READ  52480
#define OFF_BETA  54528
#define OFF_LEN   54544
#define OFF_DST   54576
#define OFF_MBAR  54608
#define OFF_M     54656
#define SMEM_TOTAL (54656 + 4 * MEMN * WORDN * 2)   // 185728 bytes

// ---------------- K1: cluster-of-2 tensor-core kernel, mbarrier sync ----------------
__global__ __launch_bounds__(512, 1) __cluster_dims__(2, 1, 1)
void ntm_main(const float* __restrict__ data, const int* __restrict__ batch_sizes,
              const int* __restrict__ unsort_idxs,
              const float* __restrict__ b_ih, const float* __restrict__ b_hh,
              const float* __restrict__ b_key, const float* __restrict__ b_beta,
              const float* __restrict__ b_erase, const float* __restrict__ b_add,
              const float* __restrict__ M0, float* __restrict__ out) {
    extern __shared__ __align__(16) unsigned char dsm[];
    __half* s_inh           = (__half*)(dsm + OFF_INH);   // [8 elem][STRX]
    __half* s_hHf           = (__half*)(dsm + OFF_HHF);   // [8 elem][STRH]
    float*  red             = (float*)(dsm + OFF_RED);    // pipe partials [4][128 jl][8 e]
    float*  redS            = (float*)(dsm + OFF_REDS);   // serial khalf0 partials [3][128][8]
    float (*s_key)[128]     = (float(*)[128])(dsm + OFF_KEY);
    float (*s_e)[128]       = (float(*)[128])(dsm + OFF_E);
    float (*s_a)[128]       = (float(*)[128])(dsm + OFF_A);
    float (*s_w)[128]       = (float(*)[128])(dsm + OFF_W);
    float (*s_racc)[4][128] = (float(*)[4][128])(dsm + OFF_RACC);  // [4 el][4 qt][128]
    float (*s_read)[128]    = (float(*)[128])(dsm + OFF_READ);
    float* s_beta           = (float*)(dsm + OFF_BETA);
    int*   s_len            = (int*)(dsm + OFF_LEN);
    int*   s_dst            = (int*)(dsm + OFF_DST);
    __half* s_M             = (__half*)(dsm + OFF_M);     // [4 local el][128][128]

    const int tid = threadIdx.x;
    const int lane = tid & 31;
    const int warp = tid >> 5;
    const int gid = lane >> 2, tig = lane & 3;
    const uint32_t rank = ctarank();
    const uint32_t peer = rank ^ 1u;
    const int b0blk = (blockIdx.x >> 1) * 8;

    const uint32_t l_base = (uint32_t)__cvta_generic_to_shared(dsm);
    const uint32_t p_base = mapa_u32(l_base, peer);
    const uint32_t l_mbH = l_base + OFF_MBAR,      p_mbH = p_base + OFF_MBAR;
    const uint32_t l_mbD = l_base + OFF_MBAR + 8,  p_mbD = p_base + OFF_MBAR + 8;
    const uint32_t l_mbR = l_base + OFF_MBAR + 16, p_mbR = p_base + OFF_MBAR + 16;
    const uint32_t p_inh  = p_base + OFF_INH;
    const uint32_t p_hHf  = p_base + OFF_HHF;

    // ---- active lengths ----
    if (warp < 8) {
        int e = warp, cnt = 0;
        for (int t = lane; t < TN; t += 32) cnt += (batch_sizes[t] > (b0blk + e)) ? 1 : 0;
        #pragma unroll
        for (int s = 16; s; s >>= 1) cnt += __shfl_xor_sync(0xffffffffu, cnt, s);
        if (lane == 0) s_len[e] = cnt;
    }
    // ---- init M ----
    for (int i = tid; i < (MEMN * WORDN) / 2; i += 512) {
        float2 f = ((const float2*)M0)[i];
        __half2 h = __floats2half2_rn(f.x, f.y);
        #pragma unroll
        for (int el = 0; el < 4; el++)
            ((__half2*)s_M)[el * ((MEMN * WORDN) / 2) + i] = h;
    }
    for (int i = tid; i < 8 * STRX; i += 512) s_inh[i] = __float2half(0.0f);
    for (int i = tid; i < 8 * STRH; i += 512) s_hHf[i] = __float2half(0.0f);
    if (tid == 0) {
        asm volatile("mbarrier.init.shared.b64 [%0], %1;" :: "r"(l_mbH), "r"(256) : "memory");
        asm volatile("mbarrier.init.shared.b64 [%0], %1;" :: "r"(l_mbD), "r"(256) : "memory");
        asm volatile("mbarrier.init.shared.b64 [%0], %1;" :: "r"(l_mbR), "r"(512) : "memory");
    }

    // ---- per-lane constants ----
    const int mpS = warp >> 1;
    const int khalf = warp & 1;
    const int mpgS = (int)rank * 8 + mpS;
    const int jlS = mpS * 16 + gid;
    const int jgS = (int)rank * 128 + jlS;
    const float bR0 = b_ih[jgS] + b_hh[jgS],             bR1 = b_ih[jgS + 8] + b_hh[jgS + 8];
    const float bZ0 = b_ih[256 + jgS] + b_hh[256 + jgS], bZ1 = b_ih[256 + jgS + 8] + b_hh[256 + jgS + 8];
    const float bNi0 = b_ih[512 + jgS],                  bNi1 = b_ih[512 + jgS + 8];
    const float bNh0 = b_hh[512 + jgS],                  bNh1 = b_hh[512 + jgS + 8];
    float bHv[4];
    if (warp < 8) {
        #pragma unroll
        for (int tt = 0; tt < 2; tt++) {
            int ht = (int)rank * 16 + warp * 2 + tt;
            #pragma unroll
            for (int rr = 0; rr < 2; rr++) {
                int oo = ht * 16 + gid + rr * 8;
                float v = (oo < 128) ? b_key[oo]
                        : (oo < 256) ? b_erase[oo - 128]
                        : (oo < 384) ? b_add[oo - 256]
                        : ((oo == 384) ? b_beta[0] : 0.0f);
                bHv[tt * 2 + rr] = v;
            }
        }
    }
    float hreg[4] = {0.f, 0.f, 0.f, 0.f};

    // module/pass2 group roles: 4 warps per local elem {2el, 2el+1, 8+2el, 9+2el}
    const int el_g = (warp < 8) ? (warp >> 1) : ((warp - 8) >> 1);
    const int qt_g = (warp < 8) ? (warp & 1) : (2 + ((warp - 8) & 1));
    const int ge_g = (int)rank * 4 + el_g;
    const int mel = warp >> 1;       // module warps 0-7
    const int half = warp & 1;

    // ---- x prefetch ----
    const int xe = tid >> 6, xd = tid & 63;
    float xreg = data[((size_t)0 * BN + (b0blk + xe)) * DINN + xd];
    __syncthreads();

    const int Le0 = s_len[2 * tig], Le1 = s_len[2 * tig + 1];
    int Tmax = 0;
    #pragma unroll
    for (int e = 0; e < 8; e++) Tmax = max(Tmax, s_len[e]);

    s_inh[xe * STRX + xd] = __float2half(xreg);
    xreg = data[((size_t)1 * BN + (b0blk + xe)) * DINN + xd];
    __syncthreads();

    // ---- prologue pipe: P_0 = gi_x(x_0) (h=0) ----
    if (warp >= 8) {
        const int mpP = warp - 8;
        const int mpgP = (int)rank * 8 + mpP;
        const int jlP = mpP * 16 + gid;
        float C[4][4];
        #pragma unroll
        for (int a = 0; a < 4; a++)
            #pragma unroll
            for (int c = 0; c < 4; c++) C[a][c] = 0.0f;
        const uint4* A = (const uint4*)gA;
        #pragma unroll 4
        for (int kt = 0; kt < 4; ++kt) {
            uint32_t b0 = *(const uint32_t*)(s_inh + gid * STRX + kt * 16 + 2 * tig);
            uint32_t b1 = *(const uint32_t*)(s_inh + gid * STRX + kt * 16 + 2 * tig + 8);
            uint4 ar = __ldg(&A[(size_t)((mpgP * 3 + 0) * 28 + kt) * 32 + lane]);
            uint4 az = __ldg(&A[(size_t)((mpgP * 3 + 1) * 28 + kt) * 32 + lane]);
            uint4 an = __ldg(&A[(size_t)((mpgP * 3 + 2) * 28 + kt) * 32 + lane]);
            MMA(C[0], ar, b0, b1); MMA(C[1], az, b0, b1); MMA(C[2], an, b0, b1);
        }
        #pragma unroll
        for (int a = 0; a < 4; a++) {
            *(float2*)&red[(a * 128 + jlP) * 8 + 2 * tig] = make_float2(C[a][0], C[a][1]);
            *(float2*)&red[(a * 128 + jlP + 8) * 8 + 2 * tig] = make_float2(C[a][2], C[a][3]);
        }
    }
    __syncthreads();
    CL_SYNC();   // mbarrier init + prologue visible cluster-wide

    for (int t = 0; t < Tmax; ++t) {
        // wait peer read_{t-1}
        if (t > 0) mb_wait(l_mbR, (t & 1) ^ 1);

        // ======== SERIAL: gi_read mma, split-k (4 kt per warp) ========
        float Cr[4] = {0, 0, 0, 0}, Cz[4] = {0, 0, 0, 0}, Cni[4] = {0, 0, 0, 0};
        {
            const uint4* A = (const uint4*)gA;
            const int ktb = 4 + 4 * khalf;
            #pragma unroll
            for (int kt = ktb; kt < ktb + 4; ++kt) {
                uint32_t b0 = *(const uint32_t*)(s_inh + gid * STRX + kt * 16 + 2 * tig);
                uint32_t b1 = *(const uint32_t*)(s_inh + gid * STRX + kt * 16 + 2 * tig + 8);
                uint4 ar = __ldg(&A[(size_t)((mpgS * 3 + 0) * 28 + kt) * 32 + lane]);
                uint4 az = __ldg(&A[(size_t)((mpgS * 3 + 1) * 28 + kt) * 32 + lane]);
                uint4 an = __ldg(&A[(size_t)((mpgS * 3 + 2) * 28 + kt) * 32 + lane]);
                MMA(Cr, ar, b0, b1);
                MMA(Cz, az, b0, b1);
                MMA(Cni, an, b0, b1);
            }
        }
        if (khalf == 0) {
            #pragma unroll
            for (int rr = 0; rr < 2; rr++) {
                int jl = jlS + rr * 8;
                *(float2*)&redS[(0 * 128 + jl) * 8 + 2 * tig] = make_float2(Cr[2 * rr], Cr[2 * rr + 1]);
                *(float2*)&redS[(1 * 128 + jl) * 8 + 2 * tig] = make_float2(Cz[2 * rr], Cz[2 * rr + 1]);
                *(float2*)&redS[(2 * 128 + jl) * 8 + 2 * tig] = make_float2(Cni[2 * rr], Cni[2 * rr + 1]);
            }
        }
        __syncthreads();   // B1

        // ---- gates (odd warps) + x-store (all) ----
        if (khalf == 1) {
            #pragma unroll
            for (int c = 0; c < 4; ++c) {
                int rr = (c >> 1) & 1;
                int jl = jlS + rr * 8;
                int jg = jgS + rr * 8;
                int ee = 2 * tig + (c & 1);
                int Lc = (c & 1) ? Le1 : Le0;
                float rp = Cr[c]  + redS[(0 * 128 + jl) * 8 + ee] + red[(0 * 128 + jl) * 8 + ee] + (rr ? bR1 : bR0);
                float zp = Cz[c]  + redS[(1 * 128 + jl) * 8 + ee] + red[(1 * 128 + jl) * 8 + ee] + (rr ? bZ1 : bZ0);
                float np = Cni[c] + redS[(2 * 128 + jl) * 8 + ee] + red[(2 * 128 + jl) * 8 + ee] + (rr ? bNi1 : bNi0);
                float nh = red[(3 * 128 + jl) * 8 + ee] + (rr ? bNh1 : bNh0);
                float r = sigf(rp);
                float z = sigf(zp);
                float n = tanhf_fast(np + r * nh);
                float h = (1.0f - z) * n + z * hreg[c];
                if (t < Lc) hreg[c] = h;
                __half hh = __float2half(hreg[c]);
                s_hHf[ee * STRH + jg] = hh;
                stc_h(p_hHf + (uint32_t)(ee * STRH + jg) * 2u, hh);
            }
            mb_arrive_peer(p_mbH);
        }
        s_inh[xe * STRX + xd] = __float2half(xreg);
        {
            int tn = min(t + 2, TN - 1);
            xreg = data[((size_t)tn * BN + (b0blk + xe)) * DINN + xd];
        }
        __syncthreads();        // B2: local h + local x visible
        mb_wait(l_mbH, t & 1);  // peer h visible

        // ======== PARALLEL ========
        if (warp >= 8) {
            // pipe: P_{t+1} = gh(h_t) + gi_x(x_{t+1})
            const int mpP = warp - 8;
            const int mpgP = (int)rank * 8 + mpP;
            const int jlP = mpP * 16 + gid;
            float C[4][4];
            #pragma unroll
            for (int a = 0; a < 4; a++)
                #pragma unroll
                for (int c = 0; c < 4; c++) C[a][c] = 0.0f;
            const uint4* A = (const uint4*)gA;
            #pragma unroll 4
            for (int kt = 0; kt < 4; ++kt) {
                uint32_t b0 = *(const uint32_t*)(s_inh + gid * STRX + kt * 16 + 2 * tig);
                uint32_t b1 = *(const uint32_t*)(s_inh + gid * STRX + kt * 16 + 2 * tig + 8);
                uint4 ar = __ldg(&A[(size_t)((mpgP * 3 + 0) * 28 + kt) * 32 + lane]);
                uint4 az = __ldg(&A[(size_t)((mpgP * 3 + 1) * 28 + kt) * 32 + lane]);
                uint4 an = __ldg(&A[(size_t)((mpgP * 3 + 2) * 28 + kt) * 32 + lane]);
                MMA(C[0], ar, b0, b1); MMA(C[1], az, b0, b1); MMA(C[2], an, b0, b1);
            }
            #pragma unroll 4
            for (int kt = 0; kt < 16; ++kt) {
                uint32_t b0 = *(const uint32_t*)(s_hHf + gid * STRH + kt * 16 + 2 * tig);
                uint32_t b1 = *(const uint32_t*)(s_hHf + gid * STRH + kt * 16 + 2 * tig + 8);
                uint4 ar = __ldg(&A[(size_t)((mpgP * 3 + 0) * 28 + 12 + kt) * 32 + lane]);
                uint4 az = __ldg(&A[(size_t)((mpgP * 3 + 1) * 28 + 12 + kt) * 32 + lane]);
                uint4 an = __ldg(&A[(size_t)((mpgP * 3 + 2) * 28 + 12 + kt) * 32 + lane]);
                MMA(C[0], ar, b0, b1); MMA(C[1], az, b0, b1); MMA(C[3], an, b0, b1);
            }
            #pragma unroll
            for (int a = 0; a < 4; a++) {
                *(float2*)&red[(a * 128 + jlP) * 8 + 2 * tig] = make_float2(C[a][0], C[a][1]);
                *(float2*)&red[(a * 128 + jlP + 8) * 8 + 2 * tig] = make_float2(C[a][2], C[a][3]);
            }
        } else {
            // ---- head mma: 2 h-tiles per warp ----
            float CH[2][4];
            #pragma unroll
            for (int tt = 0; tt < 2; tt++)
                #pragma unroll
                for (int c = 0; c < 4; c++) CH[tt][c] = 0.0f;
            const uint4* AH = (const uint4*)gAH;
            const int htb = (int)rank * 16 + warp * 2;
            #pragma unroll 4
            for (int kt = 0; kt < 16; ++kt) {
                uint32_t b0 = *(const uint32_t*)(s_hHf + gid * STRH + kt * 16 + 2 * tig);
                uint32_t b1 = *(const uint32_t*)(s_hHf + gid * STRH + kt * 16 + 2 * tig + 8);
                #pragma unroll
                for (int tt = 0; tt < 2; tt++) {
                    uint4 a = __ldg(&AH[(size_t)((htb + tt) * 16 + kt) * 32 + lane]);
                    MMA(CH[tt], a, b0, b1);
                }
            }
            #pragma unroll
            for (int tt = 0; tt < 2; tt++) {
                #pragma unroll
                for (int c = 0; c < 4; c++) {
                    int o = (htb + tt) * 16 + gid + ((c >> 1) << 3);
                    int e = 2 * tig + (c & 1);
                    float v = CH[tt][c] + bHv[tt * 2 + (c >> 1)];
                    if (o <= 384) {
                        float w;
                        int off;
                        if (o < 128)      { w = tanhf_fast(v); off = OFF_KEY + ((e & 3) * 128 + o) * 4; }
                        else if (o < 256) { w = sigf(v);       off = OFF_E + ((e & 3) * 128 + o - 128) * 4; }
                        else if (o < 384) { w = v;             off = OFF_A + ((e & 3) * 128 + o - 256) * 4; }
                        else              { w = softplusf(v);  off = OFF_BETA + (e & 3) * 4; }
                        if ((e >> 2) == (int)rank) *(float*)(dsm + off) = w;
                        else stc_f(p_base + (uint32_t)off, w);
                    }
                }
            }
            mb_arrive_peer(p_mbD);
            BARN(5, 256);            // local head writes visible
            mb_wait(l_mbD, t & 1);   // peer head half visible

            // ---- module pass1 + softmax (2 warps per local elem) ----
            if (t < s_len[ge_g]) {
                const __half* Me = s_M + mel * (MEMN * WORDN);
                {
                    int rl = lane >> 3;
                    int cc = (lane & 7) * 16;
                    float2 kx[8];
                    #pragma unroll
                    for (int i = 0; i < 8; i++)
                        kx[i] = make_float2(s_key[mel][cc + 2 * i], s_key[mel][cc + 2 * i + 1]);
                    #pragma unroll 4
                    for (int mb = half * 64; mb < half * 64 + 64; mb += 4) {
                        int m = mb + rl;
                        const uint4* Mr = (const uint4*)(Me + m * WORDN + cc);
                        uint4 u0 = Mr[0];
                        uint4 u1 = Mr[1];
                        const __half2* p0 = (const __half2*)&u0;
                        const __half2* p1 = (const __half2*)&u1;
                        float2 d2 = make_float2(0.f, 0.f), n2 = make_float2(0.f, 0.f);
                        #pragma unroll
                        for (int q = 0; q < 4; q++) {
                            float2 f0 = __half22float2(p0[q]);
                            float2 f1 = __half22float2(p1[q]);
                            ffma2(d2, f0, kx[q]);
                            ffma2(n2, f0, f0);
                            ffma2(d2, f1, kx[4 + q]);
                            ffma2(n2, f1, f1);
                        }
                        float dot = d2.x + d2.y, nrm = n2.x + n2.y;
                        #pragma unroll
                        for (int s = 1; s < 8; s <<= 1) {
                            dot += __shfl_xor_sync(0xffffffffu, dot, s);
                            nrm += __shfl_xor_sync(0xffffffffu, nrm, s);
                        }
                        if ((lane & 7) == 0) s_w[mel][m] = __fdividef(dot, sqrt_fast(nrm) + EPSF);
                    }
                }
                BARN(1 + mel, 64);
                if (half == 0) {
                    float q0 = s_key[mel][lane];
                    float q1 = s_key[mel][lane + 32];
                    float q2 = s_key[mel][lane + 64];
                    float q3 = s_key[mel][lane + 96];
                    float ss = q0 * q0 + q1 * q1 + q2 * q2 + q3 * q3;
                    #pragma unroll
                    for (int s = 16; s; s >>= 1) ss += __shfl_xor_sync(0xffffffffu, ss, s);
                    float scale = __fdividef(s_beta[mel], sqrt_fast(ss) + EPSF);
                    float v0 = scale * s_w[mel][lane];
                    float v1 = scale * s_w[mel][lane + 32];
                    float v2 = scale * s_w[mel][lane + 64];
                    float v3 = scale * s_w[mel][lane + 96];
                    float mx = fmaxf(fmaxf(v0, v1), fmaxf(v2, v3));
                    #pragma unroll
                    for (int s = 16; s; s >>= 1) mx = fmaxf(mx, __shfl_xor_sync(0xffffffffu, mx, s));
                    v0 = __expf(v0 - mx); v1 = __expf(v1 - mx);
                    v2 = __expf(v2 - mx); v3 = __expf(v3 - mx);
                    float sum = v0 + v1 + v2 + v3;
                    #pragma unroll
                    for (int s = 16; s; s >>= 1) sum += __shfl_xor_sync(0xffffffffu, sum, s);
                    float inv = __fdividef(1.0f, sum);
                    s_w[mel][lane] = v0 * inv;
                    s_w[mel][lane + 32] = v1 * inv;
                    s_w[mel][lane + 64] = v2 * inv;
                    s_w[mel][lane + 96] = v3 * inv;
                }
                BARN(1 + mel, 64);
            }
        }

        // ======== PASS2: joined, 4 warps per local elem ========
        if (t < s_len[ge_g]) {
            BARN(6 + el_g, 128);   // join: s_w/s_e/s_a ready, pipe partials written
            {
                __half* Mw = s_M + el_g * (MEMN * WORDN) + lane * 4;
                float4 e4 = *(const float4*)&s_e[el_g][lane * 4];
                float4 a4 = *(const float4*)&s_a[el_g][lane * 4];
                float2 en01 = make_float2(-e4.x, -e4.y), en23 = make_float2(-e4.z, -e4.w);
                float2 a01 = make_float2(a4.x, a4.y),    a23 = make_float2(a4.z, a4.w);
                float2 r01 = make_float2(0.f, 0.f), r23 = make_float2(0.f, 0.f);
                #pragma unroll 8
                for (int m = qt_g * 32; m < qt_g * 32 + 32; ++m) {
                    float wm = s_w[el_g][m];
                    float2 wm2 = dup2(wm);
                    uint2 u = *(uint2*)(Mw + m * WORDN);
                    __half2* hp = (__half2*)&u;
                    float2 m01 = __half22float2(hp[0]);
                    float2 m23 = __half22float2(hp[1]);
                    ffma2(r01, wm2, m01);
                    ffma2(r23, wm2, m23);
                    float2 f01 = make_float2(1.f, 1.f), f23 = make_float2(1.f, 1.f);
                    ffma2(f01, wm2, en01);
                    ffma2(f23, wm2, en23);
                    float2 w01 = make_float2(0.f, 0.f), w23 = make_float2(0.f, 0.f);
                    ffma2(w01, wm2, a01);
                    ffma2(w23, wm2, a23);
                    ffma2(w01, m01, f01);
                    ffma2(w23, m23, f23);
                    hp[0] = __floats2half2_rn(w01.x, w01.y);
                    hp[1] = __floats2half2_rn(w23.x, w23.y);
                    *(uint2*)(Mw + m * WORDN) = u;
                }
                *(float4*)&s_racc[el_g][qt_g][lane * 4] = make_float4(r01.x, r01.y, r23.x, r23.y);
            }
            BARN(6 + el_g, 128);
            // combine quarters: each warp handles 32 read positions
            {
                int w = qt_g * 32 + lane;
                float s1 = (s_racc[el_g][0][w] + s_racc[el_g][1][w])
                         + (s_racc[el_g][2][w] + s_racc[el_g][3][w]);
                s_read[el_g][w] = s1;
                __half h1 = __float2half(s1);
                s_inh[ge_g * STRX + 64 + w] = h1;
                stc_h(p_inh + (uint32_t)(ge_g * STRX + 64 + w) * 2u, h1);
            }
        }
        mb_arrive_peer(p_mbR);   // unconditional (all 16 warps, all lanes)
        __syncthreads();         // loop-end: local read rows + red partials visible
    }

    // ---- epilogue ----
    CL_SYNC();   // no peer DSMEM writes in flight at teardown
    for (int q = tid; q < BN; q += 512) {
        int u = unsort_idxs[q];
        if (u >= b0blk && u < b0blk + 8) s_dst[u - b0blk] = q;
    }
    __syncthreads();
    if (khalf == 1) {
        #pragma unroll
        for (int c = 0; c < 4; ++c) {
            int jg = jgS + ((c & 2) ? 8 : 0);
            int ee = 2 * tig + (c & 1);
            out[(size_t)s_dst[ee] * CTRLN + jg] = hreg[c];
        }
    }
    {
        int el = tid >> 7, w = tid & 127;
        int ge = (int)rank * 4 + el;
        out[(size_t)BN * CTRLN + (size_t)s_dst[ge] * WORDN + w] = s_read[el][w];
    }
}

// ---------------- launch ----------------
extern "C" void kernel_launch(void* const* d_in, const int* in_sizes, int n_in,
                              void* d_out, int out_size) {
    const float* data        = (const float*)d_in[0];
    const int*   batch_sizes = (const int*)d_in[1];
    const int*   unsort      = (const int*)d_in[2];
    const float* W_ih        = (const float*)d_in[3];
    const float* b_ih        = (const float*)d_in[4];
    const float* W_hh        = (const float*)d_in[5];
    const float* b_hh        = (const float*)d_in[6];
    const float* W_key       = (const float*)d_in[7];
    const float* b_key       = (const float*)d_in[8];
    const float* W_beta      = (const float*)d_in[9];
    const float* b_beta      = (const float*)d_in[10];
    const float* W_erase     = (const float*)d_in[11];
    const float* b_erase     = (const float*)d_in[12];
    const float* W_add       = (const float*)d_in[13];
    const float* b_add       = (const float*)d_in[14];
    const float* M0          = (const float*)d_in[15];

    cudaFuncSetAttribute(ntm_main, cudaFuncAttributeMaxDynamicSharedMemorySize, SMEM_TOTAL);
    ntm_prep<<<256, 256>>>(W_ih, W_hh, W_key, W_beta, W_erase, W_add);
    ntm_main<<<128, 512, SMEM_TOTAL>>>(data, batch_sizes, unsort,
                                       b_ih, b_hh, b_key, b_beta, b_erase, b_add,
                                       M0, (float*)d_out);
}